// round 3
// baseline (speedup 1.0000x reference)
#include <cuda_runtime.h>
#include <cuda_bf16.h>
#include <math.h>

#define T_SEQ   2048
#define HID     4096
#define NHEAD   32
#define Q_LORA  1536
#define KV_LORA 512
#define D_NOPE  128
#define D_ROPE  64
#define D_QK    192
#define D_V     128
#define EPS_RMS 1e-6f

// ---------------- scratch (device globals; no allocations allowed) ----------------
__device__ float g_qc   [T_SEQ * Q_LORA];          // 2048x1536
__device__ float g_q    [T_SEQ * NHEAD * D_QK];    // 2048x6144
__device__ float g_kva  [T_SEQ * (KV_LORA+D_ROPE)];// 2048x576
__device__ float g_comp [T_SEQ * KV_LORA];         // 2048x512
__device__ float g_krope[T_SEQ * D_ROPE];          // 2048x64
__device__ float g_wukT [NHEAD * D_NOPE * KV_LORA];// [h][d][r] 32x128x512
__device__ float g_ql   [NHEAD * T_SEQ * KV_LORA]; // [h][t][r]
__device__ float g_ov   [T_SEQ * NHEAD * D_V];     // 2048x4096

// ---------------- generic batched SGEMM: C = A @ B (row-major) ----------------
// 128x128 block tile, BK=8, 256 threads, 8x8 microtile.
// Column ownership interleaved (k*64 + tx*4 + m) for 2-phase (optimal) LDS.128.
__global__ void __launch_bounds__(256) sgemm_kernel(
    const float* __restrict__ A, int lda, long long sA,
    const float* __restrict__ B, int ldb, long long sB,
    float* __restrict__ C, int ldc, long long sC,
    int M, int N, int K)
{
    A += (long long)blockIdx.z * sA;
    B += (long long)blockIdx.z * sB;
    C += (long long)blockIdx.z * sC;

    __shared__ float As[8][128];   // transposed: As[k][m]
    __shared__ float Bs[8][128];   // Bs[k][n]

    const int tid = threadIdx.x;
    const int tx  = tid & 15;      // 16 column groups
    const int ty  = tid >> 4;      // 16 row groups
    const int row0 = blockIdx.y * 128;
    const int col0 = blockIdx.x * 128;

    const int aRow = tid >> 1;            // 0..127
    const int aCol = (tid & 1) << 2;      // 0 or 4
    const int bRow = tid >> 5;            // 0..7
    const int bCol = (tid & 31) << 2;     // 0..124

    float acc[8][8];
    #pragma unroll
    for (int i = 0; i < 8; i++)
        #pragma unroll
        for (int j = 0; j < 8; j++) acc[i][j] = 0.f;

    for (int k0 = 0; k0 < K; k0 += 8) {
        float4 av = make_float4(0.f,0.f,0.f,0.f);
        if (row0 + aRow < M)
            av = *(const float4*)(A + (size_t)(row0 + aRow)*lda + k0 + aCol);
        As[aCol+0][aRow] = av.x;
        As[aCol+1][aRow] = av.y;
        As[aCol+2][aRow] = av.z;
        As[aCol+3][aRow] = av.w;

        float4 bv;
        const float* Bp = B + (size_t)(k0 + bRow)*ldb + col0 + bCol;
        const int gc = col0 + bCol;
        if (gc + 3 < N) {
            bv = *(const float4*)Bp;
        } else {
            bv.x = (gc+0 < N) ? Bp[0] : 0.f;
            bv.y = (gc+1 < N) ? Bp[1] : 0.f;
            bv.z = (gc+2 < N) ? Bp[2] : 0.f;
            bv.w = (gc+3 < N) ? Bp[3] : 0.f;
        }
        *(float4*)&Bs[bRow][bCol] = bv;
        __syncthreads();

        #pragma unroll
        for (int kk = 0; kk < 8; kk++) {
            float a[8], b[8];
            *(float4*)&a[0] = *(const float4*)&As[kk][ty*8];
            *(float4*)&a[4] = *(const float4*)&As[kk][ty*8 + 4];
            *(float4*)&b[0] = *(const float4*)&Bs[kk][tx*4];        // cols tx*4 .. +4
            *(float4*)&b[4] = *(const float4*)&Bs[kk][64 + tx*4];   // cols 64+tx*4 .. +4
            #pragma unroll
            for (int i = 0; i < 8; i++)
                #pragma unroll
                for (int j = 0; j < 8; j++)
                    acc[i][j] += a[i]*b[j];
        }
        __syncthreads();
    }

    #pragma unroll
    for (int i = 0; i < 8; i++) {
        const int r = row0 + ty*8 + i;
        if (r >= M) continue;
        #pragma unroll
        for (int kb = 0; kb < 2; kb++) {
            const int c = col0 + kb*64 + tx*4;
            if (c + 3 < N) {
                *(float4*)(C + (size_t)r*ldc + c) =
                    make_float4(acc[i][kb*4+0], acc[i][kb*4+1], acc[i][kb*4+2], acc[i][kb*4+3]);
            } else {
                #pragma unroll
                for (int m = 0; m < 4; m++)
                    if (c + m < N) C[(size_t)r*ldc + c + m] = acc[i][kb*4+m];
            }
        }
    }
}

// ---------------- w_uk transpose: wukT[h][d][r] = w_uk[r][h][d] ----------------
__global__ void transpose_wuk_kernel(const float* __restrict__ wuk)
{
    int idx = blockIdx.x * blockDim.x + threadIdx.x;
    if (idx < KV_LORA * NHEAD * D_NOPE) {
        int r = idx >> 12;            // / (32*128)
        int h = (idx >> 7) & 31;
        int d = idx & 127;
        g_wukT[((size_t)(h*128 + d))*KV_LORA + r] = wuk[idx];
    }
}

// ---------------- block reduce helper ----------------
__device__ __forceinline__ float block_reduce_sum(float v, float* red)
{
    const int lane = threadIdx.x & 31, wid = threadIdx.x >> 5;
    #pragma unroll
    for (int o = 16; o > 0; o >>= 1) v += __shfl_xor_sync(0xffffffffu, v, o);
    if (lane == 0) red[wid] = v;
    __syncthreads();
    const int nw = blockDim.x >> 5;
    float s = (threadIdx.x < nw) ? red[threadIdx.x] : 0.f;
    if (wid == 0) {
        #pragma unroll
        for (int o = 16; o > 0; o >>= 1) s += __shfl_xor_sync(0xffffffffu, s, o);
        if (lane == 0) red[0] = s;
    }
    __syncthreads();
    return red[0];
}

// ---------------- rmsnorm in place (one block per row) ----------------
__global__ void rmsnorm_kernel(float* __restrict__ x, const float* __restrict__ scale, int N)
{
    __shared__ float red[32];
    float* xr = x + (size_t)blockIdx.x * N;
    float ss = 0.f;
    for (int i = threadIdx.x; i < N; i += blockDim.x) { float v = xr[i]; ss += v*v; }
    float tot = block_reduce_sum(ss, red);
    float r = rsqrtf(tot / (float)N + EPS_RMS);
    for (int i = threadIdx.x; i < N; i += blockDim.x) xr[i] = xr[i] * r * scale[i];
}

// ---------------- kv post: rmsnorm first 512 -> comp; rope last 64 -> krope ----------------
__global__ void kv_post_kernel(const int* __restrict__ pos, const float* __restrict__ scale)
{
    __shared__ float red[32];
    const int t = blockIdx.x;
    const float* row = g_kva + (size_t)t * (KV_LORA + D_ROPE);
    float ss = 0.f;
    for (int i = threadIdx.x; i < KV_LORA; i += blockDim.x) { float v = row[i]; ss += v*v; }
    float tot = block_reduce_sum(ss, red);
    float r = rsqrtf(tot / (float)KV_LORA + EPS_RMS);
    for (int i = threadIdx.x; i < KV_LORA; i += blockDim.x)
        g_comp[(size_t)t*KV_LORA + i] = row[i] * r * scale[i];
    if (threadIdx.x < D_ROPE/2) {
        int i = threadIdx.x;
        float p = (float)pos[t];
        float inv = __powf(10000.0f, -(float)i * (1.0f/32.0f));
        float ang = p * inv;
        float c = cosf(ang), s = sinf(ang);
        float x1 = row[KV_LORA + 2*i], x2 = row[KV_LORA + 2*i + 1];
        g_krope[(size_t)t*D_ROPE + 2*i    ] = x1*c - x2*s;
        g_krope[(size_t)t*D_ROPE + 2*i + 1] = x1*s + x2*c;
    }
}

// ---------------- rope on q (in place), block per t, 1024 threads = 32 heads x 32 pairs ----------------
__global__ void q_rope_kernel(const int* __restrict__ pos)
{
    const int t = blockIdx.x;
    const int h = threadIdx.x >> 5;
    const int i = threadIdx.x & 31;
    float* base = g_q + (size_t)t*(NHEAD*D_QK) + h*D_QK + D_NOPE;
    float p = (float)pos[t];
    float inv = __powf(10000.0f, -(float)i * (1.0f/32.0f));
    float ang = p * inv;
    float c = cosf(ang), s = sinf(ang);
    float x1 = base[2*i], x2 = base[2*i + 1];
    base[2*i    ] = x1*c - x2*s;
    base[2*i + 1] = x1*s + x2*c;
}

// ---------------- flash attention over latent (512) + rope (64), fused o_v = o_latent @ w_uv ----------------
// block: (query tile of 32, head). 256 threads: i_row = tid/8, lane8 = tid%8.
// smem: q_s[32][577] | kc[64][68] | cs[64][128] | p_s[32][65]
#define ATTN_QS_STRIDE 577
#define ATTN_OS_STRIDE 513
#define ATTN_PS_STRIDE 65
#define ATTN_SMEM_FLOATS (32*577 + 64*68 + 64*128 + 32*65)
#define ATTN_SMEM_BYTES  (ATTN_SMEM_FLOATS * 4)

__global__ void __launch_bounds__(256, 1) attn_kernel(
    const int* __restrict__ pos, const float* __restrict__ wuv)
{
    extern __shared__ float sm[];
    float* q_s = sm;                         // [32][577]
    float* kc  = sm + 32*577;                // [64][68]
    float* cs  = kc + 64*68;                 // [64][128]
    float* p_s = cs + 64*128;                // [32][65]

    const int h   = blockIdx.y;
    const int t0  = blockIdx.x * 32;
    const int tid = threadIdx.x;
    const int i_row = tid >> 3;
    const int lane8 = tid & 7;

    // load Q tile: cols 0..511 = ql_nope (absorbed), 512..575 = roped q
    for (int idx = tid; idx < 32*576; idx += 256) {
        int i = idx / 576, c = idx % 576;
        int t = t0 + i;
        float v;
        if (c < KV_LORA) v = g_ql[((size_t)h*T_SEQ + t)*KV_LORA + c];
        else             v = g_q[(size_t)t*(NHEAD*D_QK) + h*D_QK + D_NOPE + (c - KV_LORA)];
        q_s[i*ATTN_QS_STRIDE + c] = v;
    }
    __syncthreads();

    const int   myPos = pos[t0 + i_row];
    const float scale = rsqrtf(192.0f);
    float m_i = -1e30f, l_i = 0.f;
    float o_acc[64];
    #pragma unroll
    for (int k = 0; k < 64; k++) o_acc[k] = 0.f;

    const int sEnd = t0 + 32;
    for (int s0 = 0; s0 < sEnd; s0 += 64) {
        // ---------- scores ----------
        float sacc[8];
        #pragma unroll
        for (int e = 0; e < 8; e++) sacc[e] = 0.f;

        for (int c0 = 0; c0 < 576; c0 += 64) {
            for (int idx = tid; idx < 64*64; idx += 256) {
                int kk = idx & 63, j = idx >> 6;
                float v;
                if (c0 < KV_LORA) v = g_comp[(size_t)(s0 + j)*KV_LORA + c0 + kk];
                else              v = g_krope[(size_t)(s0 + j)*D_ROPE + kk];
                kc[kk*68 + j] = v;
            }
            __syncthreads();
            const float* qrow = q_s + i_row*ATTN_QS_STRIDE + c0;
            #pragma unroll 8
            for (int kk = 0; kk < 64; kk++) {
                float qa = qrow[kk];
                const float4 b0 = *(const float4*)&kc[kk*68 + lane8*4];        // j = lane8*4..+4
                const float4 b1 = *(const float4*)&kc[kk*68 + 32 + lane8*4];   // j = 32+lane8*4..+4
                sacc[0] += qa*b0.x; sacc[1] += qa*b0.y; sacc[2] += qa*b0.z; sacc[3] += qa*b0.w;
                sacc[4] += qa*b1.x; sacc[5] += qa*b1.y; sacc[6] += qa*b1.z; sacc[7] += qa*b1.w;
            }
            __syncthreads();
        }
        // mask + scale (j = kb*32 + lane8*4 + m)
        #pragma unroll
        for (int e = 0; e < 8; e++) {
            int j = (e >> 2)*32 + lane8*4 + (e & 3);
            int s = s0 + j;
            sacc[e] = (pos[s] <= myPos) ? sacc[e]*scale : -1e30f;
        }
        float mx = sacc[0];
        #pragma unroll
        for (int e = 1; e < 8; e++) mx = fmaxf(mx, sacc[e]);
        #pragma unroll
        for (int o = 1; o < 8; o <<= 1) mx = fmaxf(mx, __shfl_xor_sync(0xffffffffu, mx, o));
        const float m_new = fmaxf(m_i, mx);
        const float alpha = __expf(m_i - m_new);
        float psum = 0.f;
        #pragma unroll
        for (int e = 0; e < 8; e++) {
            int j = (e >> 2)*32 + lane8*4 + (e & 3);
            float p = __expf(sacc[e] - m_new);
            p_s[i_row*ATTN_PS_STRIDE + j] = p;
            psum += p;
        }
        l_i = l_i*alpha + psum;
        m_i = m_new;
        #pragma unroll
        for (int k = 0; k < 64; k++) o_acc[k] *= alpha;
        __syncthreads();

        // ---------- O += P @ comp (stream 128-col chunks) ----------
        for (int cb = 0; cb < 4; cb++) {
            for (int idx = tid; idx < 64*128; idx += 256) {
                int c = idx & 127, j = idx >> 7;
                cs[j*128 + c] = g_comp[(size_t)(s0 + j)*KV_LORA + cb*128 + c];
            }
            __syncthreads();
            const float* prow = p_s + i_row*ATTN_PS_STRIDE;
            float* oa = o_acc + cb*16;
            #pragma unroll 4
            for (int j = 0; j < 64; j++) {
                float pv = prow[j];
                #pragma unroll
                for (int k = 0; k < 4; k++) {
                    const float4 w = *(const float4*)&cs[j*128 + k*32 + lane8*4];
                    oa[k*4+0] += pv*w.x; oa[k*4+1] += pv*w.y;
                    oa[k*4+2] += pv*w.z; oa[k*4+3] += pv*w.w;
                }
            }
            __syncthreads();
        }
    }

    // finalize softmax denominator across the 8 lanes of the row
    #pragma unroll
    for (int o = 1; o < 8; o <<= 1) l_i += __shfl_xor_sync(0xffffffffu, l_i, o);
    const float inv_l = 1.0f / l_i;

    __syncthreads();
    float* o_s = sm;  // reuse q_s region as [32][513]
    #pragma unroll
    for (int k = 0; k < 64; k++) {
        int cb = k >> 4, e = k & 15;
        int col = cb*128 + (e >> 2)*32 + lane8*4 + (e & 3);
        o_s[i_row*ATTN_OS_STRIDE + col] = o_acc[k]*inv_l;
    }
    __syncthreads();

    // o_v[i][d] = sum_r o_s[i][r] * w_uv[r][h][d], streamed in 64-r chunks
    float outacc[16];
    #pragma unroll
    for (int e = 0; e < 16; e++) outacc[e] = 0.f;
    float* wv = kc;  // [64][128], safely inside kc+cs region, disjoint from o_s
    for (int r0 = 0; r0 < KV_LORA; r0 += 64) {
        for (int idx = tid; idx < 64*128; idx += 256) {
            int d = idx & 127, rr = idx >> 7;
            wv[rr*128 + d] = wuv[((size_t)(r0 + rr)*NHEAD + h)*D_V + d];
        }
        __syncthreads();
        const float* orow = o_s + i_row*ATTN_OS_STRIDE + r0;
        #pragma unroll 4
        for (int rr = 0; rr < 64; rr++) {
            float ovv = orow[rr];
            #pragma unroll
            for (int k = 0; k < 4; k++) {
                const float4 w = *(const float4*)&wv[rr*128 + k*32 + lane8*4];
                outacc[k*4+0] += ovv*w.x; outacc[k*4+1] += ovv*w.y;
                outacc[k*4+2] += ovv*w.z; outacc[k*4+3] += ovv*w.w;
            }
        }
        __syncthreads();
    }
    float* dst = &g_ov[(size_t)(t0 + i_row)*(NHEAD*D_V) + h*D_V];
    #pragma unroll
    for (int k = 0; k < 4; k++)
        *(float4*)&dst[k*32 + lane8*4] =
            make_float4(outacc[k*4+0], outacc[k*4+1], outacc[k*4+2], outacc[k*4+3]);
}

// ---------------- host launcher ----------------
extern "C" void kernel_launch(void* const* d_in, const int* in_sizes, int n_in,
                              void* d_out, int out_size)
{
    const float* hs     = (const float*)d_in[0];
    const int*   pos    = (const int*)  d_in[1];
    const float* w_qa   = (const float*)d_in[2];
    const float* qa_ln  = (const float*)d_in[3];
    const float* w_qb   = (const float*)d_in[4];
    const float* w_kva  = (const float*)d_in[5];
    const float* kva_ln = (const float*)d_in[6];
    const float* w_uk   = (const float*)d_in[7];
    const float* w_uv   = (const float*)d_in[8];
    const float* w_o    = (const float*)d_in[9];
    float* out = (float*)d_out;

    float *p_qc, *p_q, *p_kva, *p_wukT, *p_ql, *p_ov;
    cudaGetSymbolAddress((void**)&p_qc,   g_qc);
    cudaGetSymbolAddress((void**)&p_q,    g_q);
    cudaGetSymbolAddress((void**)&p_kva,  g_kva);
    cudaGetSymbolAddress((void**)&p_wukT, g_wukT);
    cudaGetSymbolAddress((void**)&p_ql,   g_ql);
    cudaGetSymbolAddress((void**)&p_ov,   g_ov);

    // w_uk -> [h][d][r]
    transpose_wuk_kernel<<<(KV_LORA*NHEAD*D_NOPE + 255)/256, 256>>>(w_uk);

    // q_c = rmsnorm(hs @ w_qa)
    sgemm_kernel<<<dim3(Q_LORA/128, T_SEQ/128, 1), 256>>>(
        hs, HID, 0, w_qa, Q_LORA, 0, p_qc, Q_LORA, 0, T_SEQ, Q_LORA, HID);
    rmsnorm_kernel<<<T_SEQ, 256>>>(p_qc, qa_ln, Q_LORA);

    // q = q_c @ w_qb
    sgemm_kernel<<<dim3((NHEAD*D_QK)/128, T_SEQ/128, 1), 256>>>(
        p_qc, Q_LORA, 0, w_qb, NHEAD*D_QK, 0, p_q, NHEAD*D_QK, 0, T_SEQ, NHEAD*D_QK, Q_LORA);

    // kv_a = hs @ w_kva  (N = 576, guarded last tile)
    sgemm_kernel<<<dim3((KV_LORA+D_ROPE+127)/128, T_SEQ/128, 1), 256>>>(
        hs, HID, 0, w_kva, KV_LORA+D_ROPE, 0, p_kva, KV_LORA+D_ROPE, 0,
        T_SEQ, KV_LORA+D_ROPE, HID);
    kv_post_kernel<<<T_SEQ, 256>>>(pos, kva_ln);

    // rope on q (nope cols untouched)
    q_rope_kernel<<<T_SEQ, 1024>>>(pos);

    // ql_nope[h] = q_nope[:,h,:] @ w_uk[:,h,:]^T  (batched over heads)
    sgemm_kernel<<<dim3(KV_LORA/128, T_SEQ/128, NHEAD), 256>>>(
        p_q, NHEAD*D_QK, (long long)D_QK,
        p_wukT, KV_LORA, (long long)D_NOPE*KV_LORA,
        p_ql, KV_LORA, (long long)T_SEQ*KV_LORA,
        T_SEQ, KV_LORA, D_NOPE);

    // attention + fused o_v
    cudaFuncSetAttribute(attn_kernel, cudaFuncAttributeMaxDynamicSharedMemorySize, ATTN_SMEM_BYTES);
    attn_kernel<<<dim3(T_SEQ/32, NHEAD), 256, ATTN_SMEM_BYTES>>>(pos, w_uv);

    // out = o_v @ w_o
    sgemm_kernel<<<dim3(HID/128, T_SEQ/128, 1), 256>>>(
        p_ov, NHEAD*D_V, 0, w_o, HID, 0, out, HID, 0, T_SEQ, HID, NHEAD*D_V);
}

// round 4
// speedup vs baseline: 2.1579x; 2.1579x over previous
#include <cuda_runtime.h>
#include <cuda_bf16.h>
#include <math.h>

#define T_SEQ   2048
#define HID     4096
#define NHEAD   32
#define Q_LORA  1536
#define KV_LORA 512
#define D_NOPE  128
#define D_ROPE  64
#define D_QK    192
#define D_V     128
#define D_AUG   576          /* KV_LORA + D_ROPE */
#define EPS_RMS 1e-6f

// ---------------- scratch (device globals; no allocations allowed) ----------------
__device__ float g_qc    [T_SEQ * Q_LORA];
__device__ float g_q     [T_SEQ * NHEAD * D_QK];
__device__ float g_kva   [T_SEQ * D_AUG];
__device__ float g_wukT  [NHEAD * D_NOPE * KV_LORA];            // [h][d][r]
__device__ float g_qaug  [(size_t)NHEAD * T_SEQ * D_AUG];       // [h][t][576]
__device__ float g_caug  [T_SEQ * D_AUG];                       // [s][576]
__device__ float g_scores[(size_t)NHEAD * T_SEQ * T_SEQ];       // [h][t][s] 537MB
__device__ float g_ol    [(size_t)NHEAD * T_SEQ * KV_LORA];     // [h][t][r]
__device__ float g_ov    [T_SEQ * NHEAD * D_V];

// ---------------- generic batched SGEMM: C = A @ B (row-major) ----------------
// 128x128 block tile, BK=8, 256 threads, 8x8 microtile.
// kmode=1: causal cap, K_eff = row0 + 128.
__global__ void __launch_bounds__(256) sgemm_kernel(
    const float* __restrict__ A, int lda, long long sA,
    const float* __restrict__ B, int ldb, long long sB,
    float* __restrict__ C, int ldc, long long sC,
    int M, int N, int K, int kmode)
{
    A += (long long)blockIdx.z * sA;
    B += (long long)blockIdx.z * sB;
    C += (long long)blockIdx.z * sC;

    __shared__ float As[8][128];
    __shared__ float Bs[8][128];

    const int tid = threadIdx.x;
    const int tx  = tid & 15;
    const int ty  = tid >> 4;
    const int row0 = blockIdx.y * 128;
    const int col0 = blockIdx.x * 128;

    const int aRow = tid >> 1;
    const int aCol = (tid & 1) << 2;
    const int bRow = tid >> 5;
    const int bCol = (tid & 31) << 2;

    const int Keff = kmode ? (row0 + 128) : K;

    float acc[8][8];
    #pragma unroll
    for (int i = 0; i < 8; i++)
        #pragma unroll
        for (int j = 0; j < 8; j++) acc[i][j] = 0.f;

    for (int k0 = 0; k0 < Keff; k0 += 8) {
        float4 av = make_float4(0.f,0.f,0.f,0.f);
        if (row0 + aRow < M)
            av = *(const float4*)(A + (size_t)(row0 + aRow)*lda + k0 + aCol);
        As[aCol+0][aRow] = av.x;
        As[aCol+1][aRow] = av.y;
        As[aCol+2][aRow] = av.z;
        As[aCol+3][aRow] = av.w;

        float4 bv;
        const float* Bp = B + (size_t)(k0 + bRow)*ldb + col0 + bCol;
        const int gc = col0 + bCol;
        if (gc + 3 < N) {
            bv = *(const float4*)Bp;
        } else {
            bv.x = (gc+0 < N) ? Bp[0] : 0.f;
            bv.y = (gc+1 < N) ? Bp[1] : 0.f;
            bv.z = (gc+2 < N) ? Bp[2] : 0.f;
            bv.w = (gc+3 < N) ? Bp[3] : 0.f;
        }
        *(float4*)&Bs[bRow][bCol] = bv;
        __syncthreads();

        #pragma unroll
        for (int kk = 0; kk < 8; kk++) {
            float a[8], b[8];
            *(float4*)&a[0] = *(const float4*)&As[kk][ty*8];
            *(float4*)&a[4] = *(const float4*)&As[kk][ty*8 + 4];
            *(float4*)&b[0] = *(const float4*)&Bs[kk][tx*4];
            *(float4*)&b[4] = *(const float4*)&Bs[kk][64 + tx*4];
            #pragma unroll
            for (int i = 0; i < 8; i++)
                #pragma unroll
                for (int j = 0; j < 8; j++)
                    acc[i][j] += a[i]*b[j];
        }
        __syncthreads();
    }

    #pragma unroll
    for (int i = 0; i < 8; i++) {
        const int r = row0 + ty*8 + i;
        if (r >= M) continue;
        #pragma unroll
        for (int kb = 0; kb < 2; kb++) {
            const int c = col0 + kb*64 + tx*4;
            if (c + 3 < N) {
                *(float4*)(C + (size_t)r*ldc + c) =
                    make_float4(acc[i][kb*4+0], acc[i][kb*4+1], acc[i][kb*4+2], acc[i][kb*4+3]);
            } else {
                #pragma unroll
                for (int m = 0; m < 4; m++)
                    if (c + m < N) C[(size_t)r*ldc + c + m] = acc[i][kb*4+m];
            }
        }
    }
}

// ---------------- NT scores GEMM: scores[h][t][s] = Qaug[h][t][:] . Caug[s][:] ----------------
__global__ void __launch_bounds__(256) scores_kernel()
{
    const int h    = blockIdx.z;
    const int row0 = blockIdx.y * 128;   // t
    const int col0 = blockIdx.x * 128;   // s
    if (col0 > row0 + 127) return;

    const float* A = g_qaug + (size_t)h * T_SEQ * D_AUG;
    const float* B = g_caug;
    float*       C = g_scores + (size_t)h * T_SEQ * T_SEQ;

    __shared__ float As[8][128];
    __shared__ float Bs[8][128];

    const int tid  = threadIdx.x;
    const int tx   = tid & 15;
    const int ty   = tid >> 4;
    const int aRow = tid >> 1;
    const int aCol = (tid & 1) << 2;

    float acc[8][8];
    #pragma unroll
    for (int i = 0; i < 8; i++)
        #pragma unroll
        for (int j = 0; j < 8; j++) acc[i][j] = 0.f;

    for (int k0 = 0; k0 < D_AUG; k0 += 8) {
        float4 av = *(const float4*)(A + (size_t)(row0 + aRow)*D_AUG + k0 + aCol);
        As[aCol+0][aRow] = av.x;
        As[aCol+1][aRow] = av.y;
        As[aCol+2][aRow] = av.z;
        As[aCol+3][aRow] = av.w;
        float4 bv = *(const float4*)(B + (size_t)(col0 + aRow)*D_AUG + k0 + aCol);
        Bs[aCol+0][aRow] = bv.x;
        Bs[aCol+1][aRow] = bv.y;
        Bs[aCol+2][aRow] = bv.z;
        Bs[aCol+3][aRow] = bv.w;
        __syncthreads();

        #pragma unroll
        for (int kk = 0; kk < 8; kk++) {
            float a[8], b[8];
            *(float4*)&a[0] = *(const float4*)&As[kk][ty*8];
            *(float4*)&a[4] = *(const float4*)&As[kk][ty*8 + 4];
            *(float4*)&b[0] = *(const float4*)&Bs[kk][tx*4];
            *(float4*)&b[4] = *(const float4*)&Bs[kk][64 + tx*4];
            #pragma unroll
            for (int i = 0; i < 8; i++)
                #pragma unroll
                for (int j = 0; j < 8; j++)
                    acc[i][j] += a[i]*b[j];
        }
        __syncthreads();
    }

    #pragma unroll
    for (int i = 0; i < 8; i++) {
        const int r = row0 + ty*8 + i;
        #pragma unroll
        for (int kb = 0; kb < 2; kb++) {
            const int c = col0 + kb*64 + tx*4;
            *(float4*)(C + (size_t)r*T_SEQ + c) =
                make_float4(acc[i][kb*4+0], acc[i][kb*4+1], acc[i][kb*4+2], acc[i][kb*4+3]);
        }
    }
}

// ---------------- reductions ----------------
__device__ __forceinline__ float block_reduce_sum(float v, float* red)
{
    __syncthreads();
    const int lane = threadIdx.x & 31, wid = threadIdx.x >> 5;
    #pragma unroll
    for (int o = 16; o > 0; o >>= 1) v += __shfl_xor_sync(0xffffffffu, v, o);
    if (lane == 0) red[wid] = v;
    __syncthreads();
    const int nw = blockDim.x >> 5;
    float s = (threadIdx.x < nw) ? red[threadIdx.x] : 0.f;
    if (wid == 0) {
        #pragma unroll
        for (int o = 16; o > 0; o >>= 1) s += __shfl_xor_sync(0xffffffffu, s, o);
        if (lane == 0) red[0] = s;
    }
    __syncthreads();
    return red[0];
}

__device__ __forceinline__ float block_reduce_max(float v, float* red)
{
    __syncthreads();
    const int lane = threadIdx.x & 31, wid = threadIdx.x >> 5;
    #pragma unroll
    for (int o = 16; o > 0; o >>= 1) v = fmaxf(v, __shfl_xor_sync(0xffffffffu, v, o));
    if (lane == 0) red[wid] = v;
    __syncthreads();
    const int nw = blockDim.x >> 5;
    float s = (threadIdx.x < nw) ? red[threadIdx.x] : -3.0e38f;
    if (wid == 0) {
        #pragma unroll
        for (int o = 16; o > 0; o >>= 1) s = fmaxf(s, __shfl_xor_sync(0xffffffffu, s, o));
        if (lane == 0) red[0] = s;
    }
    __syncthreads();
    return red[0];
}

// ---------------- softmax: causal mask + scale, in place; zeros up to 128-block boundary ----------------
__global__ void softmax_kernel()
{
    __shared__ float red[32];
    const int t = blockIdx.x;
    const int h = blockIdx.y;
    float* row = g_scores + ((size_t)h * T_SEQ + t) * T_SEQ;
    const int n = t + 1;
    const float scale = rsqrtf(192.0f);

    float m = -3.0e38f;
    for (int i = threadIdx.x; i < n; i += blockDim.x) m = fmaxf(m, row[i]*scale);
    m = block_reduce_max(m, red);

    float l = 0.f;
    for (int i = threadIdx.x; i < n; i += blockDim.x) l += __expf(row[i]*scale - m);
    l = block_reduce_sum(l, red);
    const float inv = 1.0f / l;

    const int kblk = ((t >> 7) + 1) << 7;
    for (int i = threadIdx.x; i < kblk; i += blockDim.x)
        row[i] = (i < n) ? __expf(row[i]*scale - m) * inv : 0.f;
}

// ---------------- w_uk transpose: wukT[h][d][r] = w_uk[r][h][d] ----------------
__global__ void transpose_wuk_kernel(const float* __restrict__ wuk)
{
    int idx = blockIdx.x * blockDim.x + threadIdx.x;
    if (idx < KV_LORA * NHEAD * D_NOPE) {
        int r = idx >> 12;
        int h = (idx >> 7) & 31;
        int d = idx & 127;
        g_wukT[((size_t)(h*128 + d))*KV_LORA + r] = wuk[idx];
    }
}

// ---------------- rmsnorm in place ----------------
__global__ void rmsnorm_kernel(float* __restrict__ x, const float* __restrict__ scale, int N)
{
    __shared__ float red[32];
    float* xr = x + (size_t)blockIdx.x * N;
    float ss = 0.f;
    for (int i = threadIdx.x; i < N; i += blockDim.x) { float v = xr[i]; ss += v*v; }
    float tot = block_reduce_sum(ss, red);
    float r = rsqrtf(tot / (float)N + EPS_RMS);
    for (int i = threadIdx.x; i < N; i += blockDim.x) xr[i] = xr[i] * r * scale[i];
}

// ---------------- kv post: rmsnorm -> caug[:,0:512]; rope -> caug[:,512:576] ----------------
__global__ void kv_post_kernel(const int* __restrict__ pos, const float* __restrict__ scale)
{
    __shared__ float red[32];
    const int t = blockIdx.x;
    const float* row = g_kva + (size_t)t * D_AUG;
    float* crow = g_caug + (size_t)t * D_AUG;
    float ss = 0.f;
    for (int i = threadIdx.x; i < KV_LORA; i += blockDim.x) { float v = row[i]; ss += v*v; }
    float tot = block_reduce_sum(ss, red);
    float r = rsqrtf(tot / (float)KV_LORA + EPS_RMS);
    for (int i = threadIdx.x; i < KV_LORA; i += blockDim.x)
        crow[i] = row[i] * r * scale[i];
    if (threadIdx.x < D_ROPE/2) {
        int i = threadIdx.x;
        float p = (float)pos[t];
        float inv = __powf(10000.0f, -(float)i * (1.0f/32.0f));
        float ang = p * inv;
        float c = cosf(ang), s = sinf(ang);
        float x1 = row[KV_LORA + 2*i], x2 = row[KV_LORA + 2*i + 1];
        crow[KV_LORA + 2*i    ] = x1*c - x2*s;
        crow[KV_LORA + 2*i + 1] = x1*s + x2*c;
    }
}

// ---------------- rope on q (in place) ----------------
__global__ void q_rope_kernel(const int* __restrict__ pos)
{
    const int t = blockIdx.x;
    const int h = threadIdx.x >> 5;
    const int i = threadIdx.x & 31;
    float* base = g_q + (size_t)t*(NHEAD*D_QK) + h*D_QK + D_NOPE;
    float p = (float)pos[t];
    float inv = __powf(10000.0f, -(float)i * (1.0f/32.0f));
    float ang = p * inv;
    float c = cosf(ang), s = sinf(ang);
    float x1 = base[2*i], x2 = base[2*i + 1];
    base[2*i    ] = x1*c - x2*s;
    base[2*i + 1] = x1*s + x2*c;
}

// ---------------- copy roped q into qaug[:, 512:576] ----------------
__global__ void qaug_rope_kernel()
{
    const int t = blockIdx.x;
    for (int idx = threadIdx.x; idx < NHEAD*D_ROPE; idx += blockDim.x) {
        int h = idx >> 6, k = idx & 63;
        g_qaug[((size_t)h*T_SEQ + t)*D_AUG + KV_LORA + k] =
            g_q[(size_t)t*(NHEAD*D_QK) + h*D_QK + D_NOPE + k];
    }
}

// ---------------- host launcher ----------------
extern "C" void kernel_launch(void* const* d_in, const int* in_sizes, int n_in,
                              void* d_out, int out_size)
{
    const float* hs     = (const float*)d_in[0];
    const int*   pos    = (const int*)  d_in[1];
    const float* w_qa   = (const float*)d_in[2];
    const float* qa_ln  = (const float*)d_in[3];
    const float* w_qb   = (const float*)d_in[4];
    const float* w_kva  = (const float*)d_in[5];
    const float* kva_ln = (const float*)d_in[6];
    const float* w_uk   = (const float*)d_in[7];
    const float* w_uv   = (const float*)d_in[8];
    const float* w_o    = (const float*)d_in[9];
    float* out = (float*)d_out;

    float *p_qc, *p_q, *p_kva, *p_wukT, *p_qaug, *p_caug, *p_scores, *p_ol, *p_ov;
    cudaGetSymbolAddress((void**)&p_qc,     g_qc);
    cudaGetSymbolAddress((void**)&p_q,      g_q);
    cudaGetSymbolAddress((void**)&p_kva,    g_kva);
    cudaGetSymbolAddress((void**)&p_wukT,   g_wukT);
    cudaGetSymbolAddress((void**)&p_qaug,   g_qaug);
    cudaGetSymbolAddress((void**)&p_caug,   g_caug);
    cudaGetSymbolAddress((void**)&p_scores, g_scores);
    cudaGetSymbolAddress((void**)&p_ol,     g_ol);
    cudaGetSymbolAddress((void**)&p_ov,     g_ov);

    // w_uk -> [h][d][r]
    transpose_wuk_kernel<<<(KV_LORA*NHEAD*D_NOPE + 255)/256, 256>>>(w_uk);

    // q_c = rmsnorm(hs @ w_qa)
    sgemm_kernel<<<dim3(Q_LORA/128, T_SEQ/128, 1), 256>>>(
        hs, HID, 0, w_qa, Q_LORA, 0, p_qc, Q_LORA, 0, T_SEQ, Q_LORA, HID, 0);
    rmsnorm_kernel<<<T_SEQ, 256>>>(p_qc, qa_ln, Q_LORA);

    // q = q_c @ w_qb
    sgemm_kernel<<<dim3((NHEAD*D_QK)/128, T_SEQ/128, 1), 256>>>(
        p_qc, Q_LORA, 0, w_qb, NHEAD*D_QK, 0, p_q, NHEAD*D_QK, 0,
        T_SEQ, NHEAD*D_QK, Q_LORA, 0);

    // rope on q
    q_rope_kernel<<<T_SEQ, 1024>>>(pos);

    // qaug[h][t][0:512] = q_nope @ w_uk^T (batched over heads)
    sgemm_kernel<<<dim3(KV_LORA/128, T_SEQ/128, NHEAD), 256>>>(
        p_q, NHEAD*D_QK, (long long)D_QK,
        p_wukT, KV_LORA, (long long)D_NOPE*KV_LORA,
        p_qaug, D_AUG, (long long)T_SEQ*D_AUG,
        T_SEQ, KV_LORA, D_NOPE, 0);

    // qaug[h][t][512:576] = roped q
    qaug_rope_kernel<<<T_SEQ, 256>>>();

    // kv_a = hs @ w_kva
    sgemm_kernel<<<dim3((D_AUG+127)/128, T_SEQ/128, 1), 256>>>(
        hs, HID, 0, w_kva, D_AUG, 0, p_kva, D_AUG, 0, T_SEQ, D_AUG, HID, 0);
    kv_post_kernel<<<T_SEQ, 256>>>(pos, kva_ln);

    // scores[h] = Qaug[h] @ Caug^T (causal tiles only)
    scores_kernel<<<dim3(T_SEQ/128, T_SEQ/128, NHEAD), 256>>>();

    // softmax (mask + scale inside)
    softmax_kernel<<<dim3(T_SEQ, NHEAD), 256>>>();

    // O[h] = P[h] @ Caug[:, :512]  (K capped at row0+128 via kmode=1)
    sgemm_kernel<<<dim3(KV_LORA/128, T_SEQ/128, NHEAD), 256>>>(
        p_scores, T_SEQ, (long long)T_SEQ*T_SEQ,
        p_caug, D_AUG, 0,
        p_ol, KV_LORA, (long long)T_SEQ*KV_LORA,
        T_SEQ, KV_LORA, T_SEQ, 1);

    // o_v[t][h*128+d] = O[h][t][:] @ w_uv[:,h,:]
    sgemm_kernel<<<dim3(1, T_SEQ/128, NHEAD), 256>>>(
        p_ol, KV_LORA, (long long)T_SEQ*KV_LORA,
        w_uv, NHEAD*D_V, (long long)D_V,
        p_ov, NHEAD*D_V, (long long)D_V,
        T_SEQ, D_V, KV_LORA, 0);

    // out = o_v @ w_o
    sgemm_kernel<<<dim3(HID/128, T_SEQ/128, 1), 256>>>(
        p_ov, NHEAD*D_V, 0, w_o, HID, 0, out, HID, 0, T_SEQ, HID, NHEAD*D_V, 0);
}

// round 5
// speedup vs baseline: 3.9853x; 1.8469x over previous
#include <cuda_runtime.h>
#include <cuda_bf16.h>
#include <math.h>
#include <stdint.h>

#define T_SEQ   2048
#define HID     4096
#define NHEAD   32
#define Q_LORA  1536
#define KV_LORA 512
#define D_NOPE  128
#define D_ROPE  64
#define D_QK    192
#define D_V     128
#define D_AUG   576
#define EPS_RMS 1e-6f

// flags bits for tgemm
#define F_KCAUSAL 1   // K_eff = row0 + 128 (PV with zero-padded P)
#define F_NT      2   // B is row-major [n][k] (scores: Caug^T)
#define F_SKIP    4   // skip blocks fully above the causal diagonal

// ---------------- scratch (device globals; no allocations allowed) ----------------
__device__ float g_qc    [T_SEQ * Q_LORA];
__device__ float g_q     [T_SEQ * NHEAD * D_QK];
__device__ float g_kva   [T_SEQ * D_AUG];
__device__ float g_wukT  [NHEAD * D_NOPE * KV_LORA];            // [h][d][r]
__device__ float g_qaug  [(size_t)NHEAD * T_SEQ * D_AUG];       // [h][t][576]
__device__ float g_caug  [T_SEQ * D_AUG];                       // [s][576]
__device__ float g_scores[(size_t)NHEAD * T_SEQ * T_SEQ];       // [h][t][s]
__device__ float g_ol    [(size_t)NHEAD * T_SEQ * KV_LORA];     // [h][t][r]
__device__ float g_ov    [T_SEQ * NHEAD * D_V];

// ---------------- helpers ----------------
__device__ __forceinline__ uint32_t f2tf(float x)
{
    uint32_t r;
    asm("cvt.rna.tf32.f32 %0, %1;" : "=r"(r) : "f"(x));
    return r;
}

__device__ __forceinline__ void mma_tf32(float c[4], const uint32_t a[4], const uint32_t b[2])
{
    asm volatile(
        "mma.sync.aligned.m16n8k8.row.col.f32.tf32.tf32.f32 "
        "{%0,%1,%2,%3}, {%4,%5,%6,%7}, {%8,%9}, {%0,%1,%2,%3};"
        : "+f"(c[0]), "+f"(c[1]), "+f"(c[2]), "+f"(c[3])
        : "r"(a[0]), "r"(a[1]), "r"(a[2]), "r"(a[3]), "r"(b[0]), "r"(b[1]));
}

// ---------------- TF32 tensor-core GEMM: C = A @ B (or A @ B^T with F_NT) ----------------
// 128x128x16 block tile, 256 threads, warp tile 64x32 (m16n8k8 fragments).
__global__ void __launch_bounds__(256, 2) tgemm_kernel(
    const float* __restrict__ A, int lda, long long sA,
    const float* __restrict__ B, int ldb, long long sB,
    float* __restrict__ C, int ldc, long long sC,
    int M, int N, int K, int flags)
{
    const int row0 = blockIdx.y * 128;
    const int col0 = blockIdx.x * 128;
    if ((flags & F_SKIP) && col0 > row0 + 127) return;

    A += (long long)blockIdx.z * sA;
    B += (long long)blockIdx.z * sB;
    C += (long long)blockIdx.z * sC;

    __shared__ uint32_t As[128 * 20];   // row-major [m][k], stride 20
    __shared__ uint32_t Bs[2560];       // NN: [k][n] stride 132 ; NT: [n][k] stride 20

    const int tid    = threadIdx.x;
    const int lane   = tid & 31;
    const int wid    = tid >> 5;
    const int warp_m = wid >> 2;        // 0..1 -> 64 rows
    const int warp_n = wid & 3;         // 0..3 -> 32 cols
    const int lg     = lane >> 2;       // group id 0..7
    const int lt     = lane & 3;        // thread-in-group

    const int Keff = (flags & F_KCAUSAL) ? (row0 + 128) : K;
    const bool nt  = (flags & F_NT) != 0;

    // A loader: thread -> row tid/2, k-offset (tid&1)*8, two float4
    const int aRow = tid >> 1;
    const int aCol = (tid & 1) << 3;
    // B loader (NN): rows tid/32 and tid/32+8, cols (tid&31)*4
    const int bK = tid >> 5;
    const int bN = (tid & 31) << 2;

    float acc[4][4][4];
    #pragma unroll
    for (int i = 0; i < 4; i++)
        #pragma unroll
        for (int j = 0; j < 4; j++)
            #pragma unroll
            for (int e = 0; e < 4; e++) acc[i][j][e] = 0.f;

    for (int k0 = 0; k0 < Keff; k0 += 16) {
        // ---- load A tile -> As[m][k] ----
        {
            float4 v0 = make_float4(0.f,0.f,0.f,0.f), v1 = v0;
            if (row0 + aRow < M) {
                const float* p = A + (size_t)(row0 + aRow)*lda + k0 + aCol;
                v0 = *(const float4*)p;
                v1 = *(const float4*)(p + 4);
            }
            uint32_t* d = &As[aRow*20 + aCol];
            d[0] = f2tf(v0.x); d[1] = f2tf(v0.y); d[2] = f2tf(v0.z); d[3] = f2tf(v0.w);
            d[4] = f2tf(v1.x); d[5] = f2tf(v1.y); d[6] = f2tf(v1.z); d[7] = f2tf(v1.w);
        }
        // ---- load B tile ----
        if (nt) {
            // B row-major [n][k]; store Bs[n][k] stride 20
            float4 v0 = make_float4(0.f,0.f,0.f,0.f), v1 = v0;
            if (col0 + aRow < N) {
                const float* p = B + (size_t)(col0 + aRow)*ldb + k0 + aCol;
                v0 = *(const float4*)p;
                v1 = *(const float4*)(p + 4);
            }
            uint32_t* d = &Bs[aRow*20 + aCol];
            d[0] = f2tf(v0.x); d[1] = f2tf(v0.y); d[2] = f2tf(v0.z); d[3] = f2tf(v0.w);
            d[4] = f2tf(v1.x); d[5] = f2tf(v1.y); d[6] = f2tf(v1.z); d[7] = f2tf(v1.w);
        } else {
            // B row-major [k][n]; store Bs[k][n] stride 132
            #pragma unroll
            for (int half = 0; half < 2; half++) {
                const int kr = bK + half*8;
                const int gc = col0 + bN;
                float4 v = make_float4(0.f,0.f,0.f,0.f);
                const float* p = B + (size_t)(k0 + kr)*ldb + gc;
                if (gc + 3 < N) {
                    v = *(const float4*)p;
                } else {
                    if (gc+0 < N) v.x = p[0];
                    if (gc+1 < N) v.y = p[1];
                    if (gc+2 < N) v.z = p[2];
                    if (gc+3 < N) v.w = p[3];
                }
                uint32_t* d = &Bs[kr*132 + bN];
                d[0] = f2tf(v.x); d[1] = f2tf(v.y); d[2] = f2tf(v.z); d[3] = f2tf(v.w);
            }
        }
        __syncthreads();

        // ---- compute: two k8 steps ----
        #pragma unroll
        for (int kk = 0; kk < 16; kk += 8) {
            uint32_t a[4][4];
            #pragma unroll
            for (int mt = 0; mt < 4; mt++) {
                const int r = warp_m*64 + mt*16 + lg;
                a[mt][0] = As[(r    )*20 + kk + lt    ];
                a[mt][1] = As[(r + 8)*20 + kk + lt    ];
                a[mt][2] = As[(r    )*20 + kk + lt + 4];
                a[mt][3] = As[(r + 8)*20 + kk + lt + 4];
            }
            uint32_t b[4][2];
            if (nt) {
                #pragma unroll
                for (int ntt = 0; ntt < 4; ntt++) {
                    const int n = warp_n*32 + ntt*8 + lg;
                    b[ntt][0] = Bs[n*20 + kk + lt    ];
                    b[ntt][1] = Bs[n*20 + kk + lt + 4];
                }
            } else {
                #pragma unroll
                for (int ntt = 0; ntt < 4; ntt++) {
                    const int n = warp_n*32 + ntt*8 + lg;
                    b[ntt][0] = Bs[(kk + lt    )*132 + n];
                    b[ntt][1] = Bs[(kk + lt + 4)*132 + n];
                }
            }
            #pragma unroll
            for (int mt = 0; mt < 4; mt++)
                #pragma unroll
                for (int ntt = 0; ntt < 4; ntt++)
                    mma_tf32(acc[mt][ntt], a[mt], b[ntt]);
        }
        __syncthreads();
    }

    // ---- epilogue ----
    #pragma unroll
    for (int mt = 0; mt < 4; mt++) {
        #pragma unroll
        for (int ntt = 0; ntt < 4; ntt++) {
            const int r = row0 + warp_m*64 + mt*16 + lg;
            const int c = col0 + warp_n*32 + ntt*8 + 2*lt;
            if (r < M) {
                if (c + 1 < N) {
                    *(float2*)(C + (size_t)r*ldc + c) = make_float2(acc[mt][ntt][0], acc[mt][ntt][1]);
                } else {
                    if (c < N) C[(size_t)r*ldc + c] = acc[mt][ntt][0];
                }
            }
            if (r + 8 < M) {
                if (c + 1 < N) {
                    *(float2*)(C + (size_t)(r+8)*ldc + c) = make_float2(acc[mt][ntt][2], acc[mt][ntt][3]);
                } else {
                    if (c < N) C[(size_t)(r+8)*ldc + c] = acc[mt][ntt][2];
                }
            }
        }
    }
}

// ---------------- reductions ----------------
__device__ __forceinline__ float block_reduce_sum(float v, float* red)
{
    __syncthreads();
    const int lane = threadIdx.x & 31, wid = threadIdx.x >> 5;
    #pragma unroll
    for (int o = 16; o > 0; o >>= 1) v += __shfl_xor_sync(0xffffffffu, v, o);
    if (lane == 0) red[wid] = v;
    __syncthreads();
    const int nw = blockDim.x >> 5;
    float s = (threadIdx.x < nw) ? red[threadIdx.x] : 0.f;
    if (wid == 0) {
        #pragma unroll
        for (int o = 16; o > 0; o >>= 1) s += __shfl_xor_sync(0xffffffffu, s, o);
        if (lane == 0) red[0] = s;
    }
    __syncthreads();
    return red[0];
}

__device__ __forceinline__ float block_reduce_max(float v, float* red)
{
    __syncthreads();
    const int lane = threadIdx.x & 31, wid = threadIdx.x >> 5;
    #pragma unroll
    for (int o = 16; o > 0; o >>= 1) v = fmaxf(v, __shfl_xor_sync(0xffffffffu, v, o));
    if (lane == 0) red[wid] = v;
    __syncthreads();
    const int nw = blockDim.x >> 5;
    float s = (threadIdx.x < nw) ? red[threadIdx.x] : -3.0e38f;
    if (wid == 0) {
        #pragma unroll
        for (int o = 16; o > 0; o >>= 1) s = fmaxf(s, __shfl_xor_sync(0xffffffffu, s, o));
        if (lane == 0) red[0] = s;
    }
    __syncthreads();
    return red[0];
}

// ---------------- softmax: causal mask + scale, in place; zeros up to 128-block boundary ----------------
__global__ void softmax_kernel()
{
    __shared__ float red[32];
    const int t = blockIdx.x;
    const int h = blockIdx.y;
    float* row = g_scores + ((size_t)h * T_SEQ + t) * T_SEQ;
    const int n = t + 1;
    const float scale = rsqrtf(192.0f);

    float m = -3.0e38f;
    for (int i = threadIdx.x; i < n; i += blockDim.x) m = fmaxf(m, row[i]*scale);
    m = block_reduce_max(m, red);

    float l = 0.f;
    for (int i = threadIdx.x; i < n; i += blockDim.x) l += __expf(row[i]*scale - m);
    l = block_reduce_sum(l, red);
    const float inv = 1.0f / l;

    const int kblk = ((t >> 7) + 1) << 7;
    for (int i = threadIdx.x; i < kblk; i += blockDim.x)
        row[i] = (i < n) ? __expf(row[i]*scale - m) * inv : 0.f;
}

// ---------------- w_uk transpose: wukT[h][d][r] = w_uk[r][h][d] ----------------
__global__ void transpose_wuk_kernel(const float* __restrict__ wuk)
{
    int idx = blockIdx.x * blockDim.x + threadIdx.x;
    if (idx < KV_LORA * NHEAD * D_NOPE) {
        int r = idx >> 12;
        int h = (idx >> 7) & 31;
        int d = idx & 127;
        g_wukT[((size_t)(h*128 + d))*KV_LORA + r] = wuk[idx];
    }
}

// ---------------- rmsnorm in place ----------------
__global__ void rmsnorm_kernel(float* __restrict__ x, const float* __restrict__ scale, int N)
{
    __shared__ float red[32];
    float* xr = x + (size_t)blockIdx.x * N;
    float ss = 0.f;
    for (int i = threadIdx.x; i < N; i += blockDim.x) { float v = xr[i]; ss += v*v; }
    float tot = block_reduce_sum(ss, red);
    float r = rsqrtf(tot / (float)N + EPS_RMS);
    for (int i = threadIdx.x; i < N; i += blockDim.x) xr[i] = xr[i] * r * scale[i];
}

// ---------------- kv post: rmsnorm -> caug[:,0:512]; rope -> caug[:,512:576] ----------------
__global__ void kv_post_kernel(const int* __restrict__ pos, const float* __restrict__ scale)
{
    __shared__ float red[32];
    const int t = blockIdx.x;
    const float* row = g_kva + (size_t)t * D_AUG;
    float* crow = g_caug + (size_t)t * D_AUG;
    float ss = 0.f;
    for (int i = threadIdx.x; i < KV_LORA; i += blockDim.x) { float v = row[i]; ss += v*v; }
    float tot = block_reduce_sum(ss, red);
    float r = rsqrtf(tot / (float)KV_LORA + EPS_RMS);
    for (int i = threadIdx.x; i < KV_LORA; i += blockDim.x)
        crow[i] = row[i] * r * scale[i];
    if (threadIdx.x < D_ROPE/2) {
        int i = threadIdx.x;
        float p = (float)pos[t];
        float inv = __powf(10000.0f, -(float)i * (1.0f/32.0f));
        float ang = p * inv;
        float c = cosf(ang), s = sinf(ang);
        float x1 = row[KV_LORA + 2*i], x2 = row[KV_LORA + 2*i + 1];
        crow[KV_LORA + 2*i    ] = x1*c - x2*s;
        crow[KV_LORA + 2*i + 1] = x1*s + x2*c;
    }
}

// ---------------- rope on q (in place) ----------------
__global__ void q_rope_kernel(const int* __restrict__ pos)
{
    const int t = blockIdx.x;
    const int h = threadIdx.x >> 5;
    const int i = threadIdx.x & 31;
    float* base = g_q + (size_t)t*(NHEAD*D_QK) + h*D_QK + D_NOPE;
    float p = (float)pos[t];
    float inv = __powf(10000.0f, -(float)i * (1.0f/32.0f));
    float ang = p * inv;
    float c = cosf(ang), s = sinf(ang);
    float x1 = base[2*i], x2 = base[2*i + 1];
    base[2*i    ] = x1*c - x2*s;
    base[2*i + 1] = x1*s + x2*c;
}

// ---------------- copy roped q into qaug[:, 512:576] ----------------
__global__ void qaug_rope_kernel()
{
    const int t = blockIdx.x;
    for (int idx = threadIdx.x; idx < NHEAD*D_ROPE; idx += blockDim.x) {
        int h = idx >> 6, k = idx & 63;
        g_qaug[((size_t)h*T_SEQ + t)*D_AUG + KV_LORA + k] =
            g_q[(size_t)t*(NHEAD*D_QK) + h*D_QK + D_NOPE + k];
    }
}

// ---------------- host launcher ----------------
extern "C" void kernel_launch(void* const* d_in, const int* in_sizes, int n_in,
                              void* d_out, int out_size)
{
    const float* hs     = (const float*)d_in[0];
    const int*   pos    = (const int*)  d_in[1];
    const float* w_qa   = (const float*)d_in[2];
    const float* qa_ln  = (const float*)d_in[3];
    const float* w_qb   = (const float*)d_in[4];
    const float* w_kva  = (const float*)d_in[5];
    const float* kva_ln = (const float*)d_in[6];
    const float* w_uk   = (const float*)d_in[7];
    const float* w_uv   = (const float*)d_in[8];
    const float* w_o    = (const float*)d_in[9];
    float* out = (float*)d_out;

    float *p_qc, *p_q, *p_kva, *p_wukT, *p_qaug, *p_caug, *p_scores, *p_ol, *p_ov;
    cudaGetSymbolAddress((void**)&p_qc,     g_qc);
    cudaGetSymbolAddress((void**)&p_q,      g_q);
    cudaGetSymbolAddress((void**)&p_kva,    g_kva);
    cudaGetSymbolAddress((void**)&p_wukT,   g_wukT);
    cudaGetSymbolAddress((void**)&p_qaug,   g_qaug);
    cudaGetSymbolAddress((void**)&p_caug,   g_caug);
    cudaGetSymbolAddress((void**)&p_scores, g_scores);
    cudaGetSymbolAddress((void**)&p_ol,     g_ol);
    cudaGetSymbolAddress((void**)&p_ov,     g_ov);

    // w_uk -> [h][d][r]
    transpose_wuk_kernel<<<(KV_LORA*NHEAD*D_NOPE + 255)/256, 256>>>(w_uk);

    // q_c = rmsnorm(hs @ w_qa)
    tgemm_kernel<<<dim3(Q_LORA/128, T_SEQ/128, 1), 256>>>(
        hs, HID, 0, w_qa, Q_LORA, 0, p_qc, Q_LORA, 0, T_SEQ, Q_LORA, HID, 0);
    rmsnorm_kernel<<<T_SEQ, 256>>>(p_qc, qa_ln, Q_LORA);

    // q = q_c @ w_qb
    tgemm_kernel<<<dim3((NHEAD*D_QK)/128, T_SEQ/128, 1), 256>>>(
        p_qc, Q_LORA, 0, w_qb, NHEAD*D_QK, 0, p_q, NHEAD*D_QK, 0,
        T_SEQ, NHEAD*D_QK, Q_LORA, 0);

    // rope on q
    q_rope_kernel<<<T_SEQ, 1024>>>(pos);

    // qaug[h][t][0:512] = q_nope @ w_uk^T (batched over heads)
    tgemm_kernel<<<dim3(KV_LORA/128, T_SEQ/128, NHEAD), 256>>>(
        p_q, NHEAD*D_QK, (long long)D_QK,
        p_wukT, KV_LORA, (long long)D_NOPE*KV_LORA,
        p_qaug, D_AUG, (long long)T_SEQ*D_AUG,
        T_SEQ, KV_LORA, D_NOPE, 0);

    // qaug[h][t][512:576] = roped q
    qaug_rope_kernel<<<T_SEQ, 256>>>();

    // kv_a = hs @ w_kva
    tgemm_kernel<<<dim3((D_AUG+127)/128, T_SEQ/128, 1), 256>>>(
        hs, HID, 0, w_kva, D_AUG, 0, p_kva, D_AUG, 0, T_SEQ, D_AUG, HID, 0);
    kv_post_kernel<<<T_SEQ, 256>>>(pos, kva_ln);

    // scores[h] = Qaug[h] @ Caug^T  (NT, causal block skip)
    tgemm_kernel<<<dim3(T_SEQ/128, T_SEQ/128, NHEAD), 256>>>(
        p_qaug, D_AUG, (long long)T_SEQ*D_AUG,
        p_caug, D_AUG, 0,
        p_scores, T_SEQ, (long long)T_SEQ*T_SEQ,
        T_SEQ, T_SEQ, D_AUG, F_NT | F_SKIP);

    // softmax (mask + scale inside; zero-pads to 128 boundary)
    softmax_kernel<<<dim3(T_SEQ, NHEAD), 256>>>();

    // O[h] = P[h] @ Caug[:, :512]  (K capped at row0+128)
    tgemm_kernel<<<dim3(KV_LORA/128, T_SEQ/128, NHEAD), 256>>>(
        p_scores, T_SEQ, (long long)T_SEQ*T_SEQ,
        p_caug, D_AUG, 0,
        p_ol, KV_LORA, (long long)T_SEQ*KV_LORA,
        T_SEQ, KV_LORA, T_SEQ, F_KCAUSAL);

    // o_v[t][h*128+d] = O[h][t][:] @ w_uv[:,h,:]
    tgemm_kernel<<<dim3(1, T_SEQ/128, NHEAD), 256>>>(
        p_ol, KV_LORA, (long long)T_SEQ*KV_LORA,
        w_uv, NHEAD*D_V, (long long)D_V,
        p_ov, NHEAD*D_V, (long long)D_V,
        T_SEQ, D_V, KV_LORA, 0);

    // out = o_v @ w_o
    tgemm_kernel<<<dim3(HID/128, T_SEQ/128, 1), 256>>>(
        p_ov, NHEAD*D_V, 0, w_o, HID, 0, out, HID, 0, T_SEQ, HID, NHEAD*D_V, 0);
}

// round 7
// speedup vs baseline: 10.1089x; 2.5366x over previous
#include <cuda_runtime.h>
#include <cuda_fp16.h>
#include <math.h>
#include <stdint.h>

#define T_SEQ   2048
#define HID     4096
#define NHEAD   32
#define Q_LORA  1536
#define KV_LORA 512
#define D_NOPE  128
#define D_ROPE  64
#define D_QK    192
#define D_V     128
#define D_AUG   576
#define EPS_RMS 1e-6f

#define F_KCAUSAL 1   // K_eff = row0 + 128 (PV with zero-padded P)
#define F_SKIP    4   // skip blocks fully above causal diagonal
#define F_HALFOUT 8   // C is __half*

// ---------------- scratch (device globals) ----------------
__device__ float  g_qc    [T_SEQ * Q_LORA];
__device__ float  g_q     [T_SEQ * NHEAD * D_QK];
__device__ float  g_kva   [T_SEQ * D_AUG];
__device__ float  g_caug  [T_SEQ * D_AUG];
__device__ float  g_scores[(size_t)NHEAD * T_SEQ * T_SEQ];       // [h][t][s] f32

__device__ __half h_hs    [T_SEQ * HID];
__device__ __half h_qc    [T_SEQ * Q_LORA];
__device__ __half h_q     [T_SEQ * NHEAD * D_QK];
__device__ __half h_wuk   [KV_LORA * NHEAD * D_NOPE];            // [r][h][d]
__device__ __half h_qaug  [(size_t)NHEAD * T_SEQ * D_AUG];       // [h][t][576]
__device__ __half h_caug  [T_SEQ * D_AUG];                       // [s][576]
__device__ __half h_compT [KV_LORA * T_SEQ];                     // [r][s]
__device__ __half h_probs [(size_t)NHEAD * T_SEQ * T_SEQ];       // [h][t][s]
__device__ __half h_ol    [(size_t)NHEAD * T_SEQ * KV_LORA];     // [h][t][r]
__device__ __half h_ov    [T_SEQ * NHEAD * D_V];
__device__ __half h_wqaT  [Q_LORA * HID];
__device__ __half h_wqbT  [(NHEAD*D_QK) * Q_LORA];
__device__ __half h_wkvaT [D_AUG * HID];
__device__ __half h_woT   [HID * HID];
__device__ __half h_wuvT  [NHEAD * D_V * KV_LORA];               // [h][d][r]

// ---------------- helpers ----------------
__device__ __forceinline__ uint32_t smem_u32(const void* p)
{
    uint32_t a;
    asm("{ .reg .u64 t; cvta.to.shared.u64 t, %1; cvt.u32.u64 %0, t; }" : "=r"(a) : "l"(p));
    return a;
}

__device__ __forceinline__ void mma16816(float c[4], const uint32_t a[4], const uint32_t b[2])
{
    asm volatile(
        "mma.sync.aligned.m16n8k16.row.col.f32.f16.f16.f32 "
        "{%0,%1,%2,%3}, {%4,%5,%6,%7}, {%8,%9}, {%0,%1,%2,%3};"
        : "+f"(c[0]), "+f"(c[1]), "+f"(c[2]), "+f"(c[3])
        : "r"(a[0]), "r"(a[1]), "r"(a[2]), "r"(a[3]), "r"(b[0]), "r"(b[1]));
}

#define LDSM_X4(r0, r1, r2, r3, addr) \
    asm volatile("ldmatrix.sync.aligned.m8n8.x4.shared.b16 {%0,%1,%2,%3}, [%4];" \
        : "=r"(r0), "=r"(r1), "=r"(r2), "=r"(r3) : "r"(addr))

__device__ __forceinline__ void cpa16(uint32_t dst, const void* src, int sz)
{
    asm volatile("cp.async.ca.shared.global [%0], [%1], 16, %2;"
        :: "r"(dst), "l"(src), "r"(sz) : "memory");
}

// load [128 rows][32 halves] tile into smem (stride 40 halves = 80B)
__device__ __forceinline__ void load_tile(
    const __half* __restrict__ src, int ld, int r0, int nvalid, int k0,
    uint32_t dst, int tid)
{
    const int row = tid >> 1;
    const int half32 = (tid & 1);             // which 32B half of the 64B row
    const __half* g = src + (size_t)(r0 + row) * ld + k0 + half32 * 16;
    const uint32_t d = dst + row * 80 + half32 * 32;
    const int sz = ((r0 + row) < nvalid) ? 16 : 0;
    cpa16(d,      g,     sz);
    cpa16(d + 16, g + 8, sz);
}

// ---------------- FP16 tensor-core GEMM: C = A @ B^T (B NT: [n][k]) ----------------
// 128x128 tile, BK=32, double-buffered cp.async, ldmatrix fragments.
__global__ void __launch_bounds__(256) hgemm(
    const __half* __restrict__ A, int lda, long long sA,
    const __half* __restrict__ B, int ldb, long long sB,
    void* __restrict__ Cv, int ldc, long long sC,
    int M, int N, int K, int flags)
{
    const int row0 = blockIdx.y * 128;
    const int col0 = blockIdx.x * 128;
    if ((flags & F_SKIP) && col0 > row0 + 127) return;
    A += (long long)blockIdx.z * sA;
    B += (long long)blockIdx.z * sB;

    __shared__ __align__(16) __half smA[2][128 * 40];
    __shared__ __align__(16) __half smB[2][128 * 40];

    const int tid    = threadIdx.x;
    const int lane   = tid & 31;
    const int wid    = tid >> 5;
    const int warp_m = wid >> 2;              // 0..1
    const int warp_n = wid & 3;               // 0..3
    const int lg     = lane >> 2;
    const int lt     = lane & 3;
    const int lq     = lane >> 3;             // 0..3 (ldmatrix quad)
    const int lr     = lane & 7;

    const int Keff = (flags & F_KCAUSAL) ? (row0 + 128) : K;
    const int nk   = Keff >> 5;

    float acc[4][4][4];
    #pragma unroll
    for (int i = 0; i < 4; i++)
        #pragma unroll
        for (int j = 0; j < 4; j++)
            #pragma unroll
            for (int e = 0; e < 4; e++) acc[i][j][e] = 0.f;

    // prefetch tile 0
    load_tile(A, lda, row0, M, 0, smem_u32(smA[0]), tid);
    load_tile(B, ldb, col0, N, 0, smem_u32(smB[0]), tid);
    asm volatile("cp.async.commit_group;" ::: "memory");

    for (int i = 0; i < nk; i++) {
        const int b = i & 1;
        if (i + 1 < nk) {
            load_tile(A, lda, row0, M, (i + 1) * 32, smem_u32(smA[1 - b]), tid);
            load_tile(B, ldb, col0, N, (i + 1) * 32, smem_u32(smB[1 - b]), tid);
            asm volatile("cp.async.commit_group;" ::: "memory");
            asm volatile("cp.async.wait_group 1;" ::: "memory");
        } else {
            asm volatile("cp.async.wait_group 0;" ::: "memory");
        }
        __syncthreads();

        const uint32_t sA_ = smem_u32(smA[b]);
        const uint32_t sB_ = smem_u32(smB[b]);

        #pragma unroll
        for (int kk = 0; kk < 32; kk += 16) {
            uint32_t af[4][4];
            #pragma unroll
            for (int mt = 0; mt < 4; mt++) {
                const int r = warp_m * 64 + mt * 16 + (lq & 1) * 8 + lr;
                const uint32_t addr = sA_ + (r * 40 + kk + (lq >> 1) * 8) * 2;
                LDSM_X4(af[mt][0], af[mt][1], af[mt][2], af[mt][3], addr);
            }
            uint32_t bf[2][4];
            #pragma unroll
            for (int np = 0; np < 2; np++) {
                const int n = warp_n * 32 + np * 16 + (lq >> 1) * 8 + lr;
                const uint32_t addr = sB_ + (n * 40 + kk + (lq & 1) * 8) * 2;
                LDSM_X4(bf[np][0], bf[np][1], bf[np][2], bf[np][3], addr);
            }
            #pragma unroll
            for (int mt = 0; mt < 4; mt++)
                #pragma unroll
                for (int nt = 0; nt < 4; nt++)
                    mma16816(acc[mt][nt], af[mt], &bf[nt >> 1][(nt & 1) * 2]);
        }
        __syncthreads();
    }

    // ---- epilogue ----
    if (flags & F_HALFOUT) {
        __half* C = (__half*)Cv + (long long)blockIdx.z * sC;
        #pragma unroll
        for (int mt = 0; mt < 4; mt++)
            #pragma unroll
            for (int nt = 0; nt < 4; nt++) {
                const int r = row0 + warp_m * 64 + mt * 16 + lg;
                const int c = col0 + warp_n * 32 + nt * 8 + 2 * lt;
                if (c + 1 < N) {
                    if (r < M)
                        *(__half2*)(C + (size_t)r * ldc + c) =
                            __floats2half2_rn(acc[mt][nt][0], acc[mt][nt][1]);
                    if (r + 8 < M)
                        *(__half2*)(C + (size_t)(r + 8) * ldc + c) =
                            __floats2half2_rn(acc[mt][nt][2], acc[mt][nt][3]);
                }
            }
    } else {
        float* C = (float*)Cv + (long long)blockIdx.z * sC;
        #pragma unroll
        for (int mt = 0; mt < 4; mt++)
            #pragma unroll
            for (int nt = 0; nt < 4; nt++) {
                const int r = row0 + warp_m * 64 + mt * 16 + lg;
                const int c = col0 + warp_n * 32 + nt * 8 + 2 * lt;
                if (c + 1 < N) {
                    if (r < M)
                        *(float2*)(C + (size_t)r * ldc + c) =
                            make_float2(acc[mt][nt][0], acc[mt][nt][1]);
                    if (r + 8 < M)
                        *(float2*)(C + (size_t)(r + 8) * ldc + c) =
                            make_float2(acc[mt][nt][2], acc[mt][nt][3]);
                }
            }
    }
}

// ---------------- f32 -> f16 convert ----------------
__global__ void cvt_f2h(const float* __restrict__ src, __half* __restrict__ dst, int n)
{
    int i = (blockIdx.x * blockDim.x + threadIdx.x) * 4;
    if (i < n) {
        float4 v = *(const float4*)(src + i);
        *(__half2*)(dst + i)     = __floats2half2_rn(v.x, v.y);
        *(__half2*)(dst + i + 2) = __floats2half2_rn(v.z, v.w);
    }
}

// ---------------- transpose f32 -> f16: dst[c][r] = src[r][c] ----------------
__global__ void transpose_kh(const float* __restrict__ src, int ld_src,
                             __half* __restrict__ dst, int R, int Cc)
{
    __shared__ float t[32][33];
    const int c0 = blockIdx.x * 32, r0 = blockIdx.y * 32;
    const int x = threadIdx.x, y = threadIdx.y;
    #pragma unroll
    for (int j = 0; j < 32; j += 8) {
        int r = r0 + y + j, c = c0 + x;
        t[y + j][x] = (r < R && c < Cc) ? src[(size_t)r * ld_src + c] : 0.f;
    }
    __syncthreads();
    #pragma unroll
    for (int j = 0; j < 32; j += 8) {
        int c = c0 + y + j, r = r0 + x;
        if (c < Cc && r < R) dst[(size_t)c * R + r] = __float2half(t[x][y + j]);
    }
}

// ---------------- w_uv -> [h][d][r] f16 ----------------
__global__ void transpose_wuv_h(const float* __restrict__ wuv)
{
    int idx = blockIdx.x * blockDim.x + threadIdx.x;
    if (idx < KV_LORA * NHEAD * D_V) {
        int r = idx >> 12;
        int h = (idx >> 7) & 31;
        int d = idx & 127;
        h_wuvT[((size_t)(h * 128 + d)) * KV_LORA + r] = __float2half(wuv[idx]);
    }
}

// ---------------- reductions ----------------
__device__ __forceinline__ float block_reduce_sum(float v, float* red)
{
    __syncthreads();
    const int lane = threadIdx.x & 31, wid = threadIdx.x >> 5;
    #pragma unroll
    for (int o = 16; o > 0; o >>= 1) v += __shfl_xor_sync(0xffffffffu, v, o);
    if (lane == 0) red[wid] = v;
    __syncthreads();
    const int nw = blockDim.x >> 5;
    float s = (threadIdx.x < nw) ? red[threadIdx.x] : 0.f;
    if (wid == 0) {
        #pragma unroll
        for (int o = 16; o > 0; o >>= 1) s += __shfl_xor_sync(0xffffffffu, s, o);
        if (lane == 0) red[0] = s;
    }
    __syncthreads();
    return red[0];
}

__device__ __forceinline__ float block_reduce_max(float v, float* red)
{
    __syncthreads();
    const int lane = threadIdx.x & 31, wid = threadIdx.x >> 5;
    #pragma unroll
    for (int o = 16; o > 0; o >>= 1) v = fmaxf(v, __shfl_xor_sync(0xffffffffu, v, o));
    if (lane == 0) red[wid] = v;
    __syncthreads();
    const int nw = blockDim.x >> 5;
    float s = (threadIdx.x < nw) ? red[threadIdx.x] : -3.0e38f;
    if (wid == 0) {
        #pragma unroll
        for (int o = 16; o > 0; o >>= 1) s = fmaxf(s, __shfl_xor_sync(0xffffffffu, s, o));
        if (lane == 0) red[0] = s;
    }
    __syncthreads();
    return red[0];
}

// ---------------- softmax: reads f32 scores, writes f16 probs (zero-pad to 128) ----------------
__global__ void softmax_kernel()
{
    __shared__ float red[32];
    const int t = blockIdx.x;
    const int h = blockIdx.y;
    const float* row = g_scores + ((size_t)h * T_SEQ + t) * T_SEQ;
    __half* orow = h_probs + ((size_t)h * T_SEQ + t) * T_SEQ;
    const int n = t + 1;
    const float scale = rsqrtf(192.0f);

    float m = -3.0e38f;
    for (int i = threadIdx.x; i < n; i += blockDim.x) m = fmaxf(m, row[i] * scale);
    m = block_reduce_max(m, red);

    float l = 0.f;
    for (int i = threadIdx.x; i < n; i += blockDim.x) l += __expf(row[i] * scale - m);
    l = block_reduce_sum(l, red);
    const float inv = 1.0f / l;

    const int kblk = ((t >> 7) + 1) << 7;
    for (int i = threadIdx.x; i < kblk; i += blockDim.x)
        orow[i] = __float2half((i < n) ? __expf(row[i] * scale - m) * inv : 0.f);
}

// ---------------- rmsnorm: f32 in -> f16 out ----------------
__global__ void rmsnorm_h(const float* __restrict__ x, const float* __restrict__ scale,
                          __half* __restrict__ out, int N)
{
    __shared__ float red[32];
    const float* xr = x + (size_t)blockIdx.x * N;
    __half* orow = out + (size_t)blockIdx.x * N;
    float ss = 0.f;
    for (int i = threadIdx.x; i < N; i += blockDim.x) { float v = xr[i]; ss += v * v; }
    float tot = block_reduce_sum(ss, red);
    float r = rsqrtf(tot / (float)N + EPS_RMS);
    for (int i = threadIdx.x; i < N; i += blockDim.x)
        orow[i] = __float2half(xr[i] * r * scale[i]);
}

// ---------------- kv post: rmsnorm -> caug[:,0:512]; rope -> caug[:,512:576] (f32) ----------------
__global__ void kv_post_kernel(const int* __restrict__ pos, const float* __restrict__ scale)
{
    __shared__ float red[32];
    const int t = blockIdx.x;
    const float* row = g_kva + (size_t)t * D_AUG;
    float* crow = g_caug + (size_t)t * D_AUG;
    float ss = 0.f;
    for (int i = threadIdx.x; i < KV_LORA; i += blockDim.x) { float v = row[i]; ss += v * v; }
    float tot = block_reduce_sum(ss, red);
    float r = rsqrtf(tot / (float)KV_LORA + EPS_RMS);
    for (int i = threadIdx.x; i < KV_LORA; i += blockDim.x)
        crow[i] = row[i] * r * scale[i];
    if (threadIdx.x < D_ROPE / 2) {
        int i = threadIdx.x;
        float p = (float)pos[t];
        float inv = __powf(10000.0f, -(float)i * (1.0f / 32.0f));
        float ang = p * inv;
        float c = cosf(ang), s = sinf(ang);
        float x1 = row[KV_LORA + 2*i], x2 = row[KV_LORA + 2*i + 1];
        crow[KV_LORA + 2*i    ] = x1 * c - x2 * s;
        crow[KV_LORA + 2*i + 1] = x1 * s + x2 * c;
    }
}

// ---------------- rope on q (f32, in place) ----------------
__global__ void q_rope_kernel(const int* __restrict__ pos)
{
    const int t = blockIdx.x;
    const int h = threadIdx.x >> 5;
    const int i = threadIdx.x & 31;
    float* base = g_q + (size_t)t * (NHEAD * D_QK) + h * D_QK + D_NOPE;
    float p = (float)pos[t];
    float inv = __powf(10000.0f, -(float)i * (1.0f / 32.0f));
    float ang = p * inv;
    float c = cosf(ang), s = sinf(ang);
    float x1 = base[2*i], x2 = base[2*i + 1];
    base[2*i    ] = x1 * c - x2 * s;
    base[2*i + 1] = x1 * s + x2 * c;
}

// ---------------- copy roped q into h_qaug[:, 512:576] ----------------
__global__ void qaug_rope_kernel()
{
    const int t = blockIdx.x;
    for (int idx = threadIdx.x; idx < NHEAD * D_ROPE; idx += blockDim.x) {
        int h = idx >> 6, k = idx & 63;
        h_qaug[((size_t)h * T_SEQ + t) * D_AUG + KV_LORA + k] =
            __float2half(g_q[(size_t)t * (NHEAD * D_QK) + h * D_QK + D_NOPE + k]);
    }
}

// ---------------- host launcher ----------------
extern "C" void kernel_launch(void* const* d_in, const int* in_sizes, int n_in,
                              void* d_out, int out_size)
{
    const float* hs     = (const float*)d_in[0];
    const int*   pos    = (const int*)  d_in[1];
    const float* w_qa   = (const float*)d_in[2];
    const float* qa_ln  = (const float*)d_in[3];
    const float* w_qb   = (const float*)d_in[4];
    const float* w_kva  = (const float*)d_in[5];
    const float* kva_ln = (const float*)d_in[6];
    const float* w_uk   = (const float*)d_in[7];
    const float* w_uv   = (const float*)d_in[8];
    const float* w_o    = (const float*)d_in[9];
    float* out = (float*)d_out;

    float  *p_qc, *p_q, *p_kva, *p_caug, *p_scores;
    __half *p_hs, *p_hqc, *p_hq, *p_hwuk, *p_hqaug, *p_hcaug, *p_hcompT,
           *p_hprobs, *p_hol, *p_hov, *p_wqaT, *p_wqbT, *p_wkvaT, *p_woT, *p_wuvT;
    cudaGetSymbolAddress((void**)&p_qc,     g_qc);
    cudaGetSymbolAddress((void**)&p_q,      g_q);
    cudaGetSymbolAddress((void**)&p_kva,    g_kva);
    cudaGetSymbolAddress((void**)&p_caug,   g_caug);
    cudaGetSymbolAddress((void**)&p_scores, g_scores);
    cudaGetSymbolAddress((void**)&p_hs,     h_hs);
    cudaGetSymbolAddress((void**)&p_hqc,    h_qc);
    cudaGetSymbolAddress((void**)&p_hq,     h_q);
    cudaGetSymbolAddress((void**)&p_hwuk,   h_wuk);
    cudaGetSymbolAddress((void**)&p_hqaug,  h_qaug);
    cudaGetSymbolAddress((void**)&p_hcaug,  h_caug);
    cudaGetSymbolAddress((void**)&p_hcompT, h_compT);
    cudaGetSymbolAddress((void**)&p_hprobs, h_probs);
    cudaGetSymbolAddress((void**)&p_hol,    h_ol);
    cudaGetSymbolAddress((void**)&p_hov,    h_ov);
    cudaGetSymbolAddress((void**)&p_wqaT,   h_wqaT);
    cudaGetSymbolAddress((void**)&p_wqbT,   h_wqbT);
    cudaGetSymbolAddress((void**)&p_wkvaT,  h_wkvaT);
    cudaGetSymbolAddress((void**)&p_woT,    h_woT);
    cudaGetSymbolAddress((void**)&p_wuvT,   h_wuvT);

    dim3 tb(32, 8);
    // operand prep (f16 conversions / transposes)
    cvt_f2h<<<(T_SEQ*HID/4 + 255)/256, 256>>>(hs, p_hs, T_SEQ*HID);
    transpose_kh<<<dim3(Q_LORA/32, HID/32), tb>>>(w_qa, Q_LORA, p_wqaT, HID, Q_LORA);
    transpose_kh<<<dim3((NHEAD*D_QK)/32, Q_LORA/32), tb>>>(w_qb, NHEAD*D_QK, p_wqbT, Q_LORA, NHEAD*D_QK);
    transpose_kh<<<dim3(D_AUG/32, HID/32), tb>>>(w_kva, D_AUG, p_wkvaT, HID, D_AUG);
    transpose_kh<<<dim3(HID/32, HID/32), tb>>>(w_o, HID, p_woT, HID, HID);
    cvt_f2h<<<(KV_LORA*NHEAD*D_NOPE/4 + 255)/256, 256>>>(w_uk, p_hwuk, KV_LORA*NHEAD*D_NOPE);
    transpose_wuv_h<<<(KV_LORA*NHEAD*D_V + 255)/256, 256>>>(w_uv);

    // q_c = rmsnorm(hs @ w_qa) -> f16
    hgemm<<<dim3(Q_LORA/128, T_SEQ/128, 1), 256>>>(
        p_hs, HID, 0, p_wqaT, HID, 0, p_qc, Q_LORA, 0, T_SEQ, Q_LORA, HID, 0);
    rmsnorm_h<<<T_SEQ, 256>>>(p_qc, qa_ln, p_hqc, Q_LORA);

    // q = q_c @ w_qb (f32 for rope)
    hgemm<<<dim3((NHEAD*D_QK)/128, T_SEQ/128, 1), 256>>>(
        p_hqc, Q_LORA, 0, p_wqbT, Q_LORA, 0, p_q, NHEAD*D_QK, 0,
        T_SEQ, NHEAD*D_QK, Q_LORA, 0);
    q_rope_kernel<<<T_SEQ, 1024>>>(pos);
    cvt_f2h<<<(T_SEQ*NHEAD*D_QK/4 + 255)/256, 256>>>(p_q, p_hq, T_SEQ*NHEAD*D_QK);

    // qaug[h][:,0:512] = q_nope[:,h,:] @ w_uk[:,h,:]^T  -> f16
    hgemm<<<dim3(KV_LORA/128, T_SEQ/128, NHEAD), 256>>>(
        p_hq, NHEAD*D_QK, (long long)D_QK,
        p_hwuk, NHEAD*D_NOPE, (long long)D_NOPE,
        p_hqaug, D_AUG, (long long)T_SEQ*D_AUG,
        T_SEQ, KV_LORA, D_NOPE, F_HALFOUT);
    qaug_rope_kernel<<<T_SEQ, 256>>>();

    // kv_a = hs @ w_kva (f32), then rmsnorm+rope -> caug f32
    hgemm<<<dim3((D_AUG+127)/128, T_SEQ/128, 1), 256>>>(
        p_hs, HID, 0, p_wkvaT, HID, 0, p_kva, D_AUG, 0, T_SEQ, D_AUG, HID, 0);
    kv_post_kernel<<<T_SEQ, 256>>>(pos, kva_ln);
    cvt_f2h<<<(T_SEQ*D_AUG/4 + 255)/256, 256>>>(p_caug, p_hcaug, T_SEQ*D_AUG);
    transpose_kh<<<dim3(KV_LORA/32, T_SEQ/32), tb>>>(p_caug, D_AUG, p_hcompT, T_SEQ, KV_LORA);

    // scores[h] = Qaug[h] @ Caug^T  (f32 out, causal block skip)
    hgemm<<<dim3(T_SEQ/128, T_SEQ/128, NHEAD), 256>>>(
        p_hqaug, D_AUG, (long long)T_SEQ*D_AUG,
        p_hcaug, D_AUG, 0,
        p_scores, T_SEQ, (long long)T_SEQ*T_SEQ,
        T_SEQ, T_SEQ, D_AUG, F_SKIP);

    // softmax -> f16 probs (zero-padded to 128 boundary)
    softmax_kernel<<<dim3(T_SEQ, NHEAD), 256>>>();

    // O[h] = P[h] @ comp  -> f16 (K capped at row0+128)
    hgemm<<<dim3(KV_LORA/128, T_SEQ/128, NHEAD), 256>>>(
        p_hprobs, T_SEQ, (long long)T_SEQ*T_SEQ,
        p_hcompT, T_SEQ, 0,
        p_hol, KV_LORA, (long long)T_SEQ*KV_LORA,
        T_SEQ, KV_LORA, T_SEQ, F_KCAUSAL | F_HALFOUT);

    // o_v[:, h*128:(h+1)*128] = O[h] @ w_uv[:,h,:]  -> f16
    hgemm<<<dim3(1, T_SEQ/128, NHEAD), 256>>>(
        p_hol, KV_LORA, (long long)T_SEQ*KV_LORA,
        p_wuvT, KV_LORA, (long long)D_V*KV_LORA,
        p_hov, NHEAD*D_V, (long long)D_V,
        T_SEQ, D_V, KV_LORA, F_HALFOUT);

    // out = o_v @ w_o (f32)
    hgemm<<<dim3(HID/128, T_SEQ/128, 1), 256>>>(
        p_hov, NHEAD*D_V, 0, p_woT, NHEAD*D_V, 0, out, HID, 0,
        T_SEQ, HID, NHEAD*D_V, 0);
}

// round 8
// speedup vs baseline: 10.4676x; 1.0355x over previous
#include <cuda_runtime.h>
#include <cuda_fp16.h>
#include <math.h>
#include <stdint.h>

#define T_SEQ   2048
#define HID     4096
#define NHEAD   32
#define Q_LORA  1536
#define KV_LORA 512
#define D_NOPE  128
#define D_ROPE  64
#define D_QK    192
#define D_V     128
#define D_AUG   576
#define EPS_RMS 1e-6f

#define F_KCAUSAL 1   // K_eff = row0 + 128 (PV with zero-padded P)
#define F_SKIP    4   // skip blocks fully above causal diagonal
#define F_HALFOUT 8   // C is __half*

// ---------------- scratch (device globals) ----------------
__device__ float  g_qc    [T_SEQ * Q_LORA];
__device__ float  g_q     [T_SEQ * NHEAD * D_QK];
__device__ float  g_kva   [T_SEQ * D_AUG];
__device__ float  g_caug  [T_SEQ * D_AUG];
__device__ float  g_scores[(size_t)NHEAD * T_SEQ * T_SEQ];       // [h][t][s] f32

__device__ __half h_hs    [T_SEQ * HID];
__device__ __half h_qc    [T_SEQ * Q_LORA];
__device__ __half h_q     [T_SEQ * NHEAD * D_QK];
__device__ __half h_wuk   [KV_LORA * NHEAD * D_NOPE];            // [r][h][d]
__device__ __half h_qaug  [(size_t)NHEAD * T_SEQ * D_AUG];       // [h][t][576]
__device__ __half h_caug  [T_SEQ * D_AUG];                       // [s][576]
__device__ __half h_compT [KV_LORA * T_SEQ];                     // [r][s]
__device__ __half h_probs [(size_t)NHEAD * T_SEQ * T_SEQ];       // [h][t][s]
__device__ __half h_ol    [(size_t)NHEAD * T_SEQ * KV_LORA];     // [h][t][r]
__device__ __half h_ov    [T_SEQ * NHEAD * D_V];
__device__ __half h_wqaT  [Q_LORA * HID];
__device__ __half h_wqbT  [(NHEAD*D_QK) * Q_LORA];
__device__ __half h_wkvaT [D_AUG * HID];
__device__ __half h_woT   [HID * HID];
__device__ __half h_wuvT  [NHEAD * D_V * KV_LORA];               // [h][d][r]

// ---------------- helpers ----------------
__device__ __forceinline__ uint32_t smem_u32(const void* p)
{
    uint32_t a;
    asm("{ .reg .u64 t; cvta.to.shared.u64 t, %1; cvt.u32.u64 %0, t; }" : "=r"(a) : "l"(p));
    return a;
}

__device__ __forceinline__ void mma16816(float c[4], const uint32_t a[4], const uint32_t b[2])
{
    asm volatile(
        "mma.sync.aligned.m16n8k16.row.col.f32.f16.f16.f32 "
        "{%0,%1,%2,%3}, {%4,%5,%6,%7}, {%8,%9}, {%0,%1,%2,%3};"
        : "+f"(c[0]), "+f"(c[1]), "+f"(c[2]), "+f"(c[3])
        : "r"(a[0]), "r"(a[1]), "r"(a[2]), "r"(a[3]), "r"(b[0]), "r"(b[1]));
}

#define LDSM_X4(r0, r1, r2, r3, addr) \
    asm volatile("ldmatrix.sync.aligned.m8n8.x4.shared.b16 {%0,%1,%2,%3}, [%4];" \
        : "=r"(r0), "=r"(r1), "=r"(r2), "=r"(r3) : "r"(addr))

__device__ __forceinline__ void cpa16(uint32_t dst, const void* src, int sz)
{
    asm volatile("cp.async.ca.shared.global [%0], [%1], 16, %2;"
        :: "r"(dst), "l"(src), "r"(sz) : "memory");
}

// load [128 rows][32 halves] tile into smem (stride 40 halves = 80B)
__device__ __forceinline__ void load_tile(
    const __half* __restrict__ src, int ld, int r0, int nvalid, int k0,
    uint32_t dst, int tid)
{
    const int row = tid >> 1;
    const int half32 = (tid & 1);
    const __half* g = src + (size_t)(r0 + row) * ld + k0 + half32 * 16;
    const uint32_t d = dst + row * 80 + half32 * 32;
    const int sz = ((r0 + row) < nvalid) ? 16 : 0;
    cpa16(d,      g,     sz);
    cpa16(d + 16, g + 8, sz);
}

// ---------------- FP16 tensor-core GEMM: C = A @ B^T (B NT: [n][k]) ----------------
// 128x128 tile, BK=32, 3-stage cp.async pipeline, ldmatrix fragments.
#define STAGE_H (128 * 40)            // halves per operand per stage
#define HG_SMEM (3 * STAGE_H * 2 * 2) // bytes total (A+B, 3 stages)

__global__ void __launch_bounds__(256, 2) hgemm(
    const __half* __restrict__ A, int lda, long long sA,
    const __half* __restrict__ B, int ldb, long long sB,
    void* __restrict__ Cv, int ldc, long long sC,
    int M, int N, int K, int flags)
{
    const int row0 = blockIdx.y * 128;
    const int col0 = blockIdx.x * 128;
    if ((flags & F_SKIP) && col0 > row0 + 127) return;
    A += (long long)blockIdx.z * sA;
    B += (long long)blockIdx.z * sB;

    extern __shared__ __half dsm[];
    const uint32_t baseA = smem_u32(dsm);
    const uint32_t baseB = baseA + 3 * STAGE_H * 2;

    const int tid    = threadIdx.x;
    const int lane   = tid & 31;
    const int wid    = tid >> 5;
    const int warp_m = wid >> 2;
    const int warp_n = wid & 3;
    const int lg     = lane >> 2;
    const int lt     = lane & 3;
    const int lq     = lane >> 3;
    const int lr     = lane & 7;

    const int Keff = (flags & F_KCAUSAL) ? (row0 + 128) : K;
    const int nk   = Keff >> 5;

    float acc[4][4][4];
    #pragma unroll
    for (int i = 0; i < 4; i++)
        #pragma unroll
        for (int j = 0; j < 4; j++)
            #pragma unroll
            for (int e = 0; e < 4; e++) acc[i][j][e] = 0.f;

    // preload stages 0,1
    load_tile(A, lda, row0, M, 0, baseA, tid);
    load_tile(B, ldb, col0, N, 0, baseB, tid);
    asm volatile("cp.async.commit_group;" ::: "memory");
    if (nk > 1) {
        load_tile(A, lda, row0, M, 32, baseA + STAGE_H * 2, tid);
        load_tile(B, ldb, col0, N, 32, baseB + STAGE_H * 2, tid);
        asm volatile("cp.async.commit_group;" ::: "memory");
    }

    int sidx = 0;  // stage of tile i
    for (int i = 0; i < nk; i++) {
        if (i + 2 < nk) {
            const int s2 = (sidx + 2) % 3;
            load_tile(A, lda, row0, M, (i + 2) * 32, baseA + s2 * STAGE_H * 2, tid);
            load_tile(B, ldb, col0, N, (i + 2) * 32, baseB + s2 * STAGE_H * 2, tid);
            asm volatile("cp.async.commit_group;" ::: "memory");
            asm volatile("cp.async.wait_group 2;" ::: "memory");
        } else if (i + 1 < nk) {
            asm volatile("cp.async.wait_group 1;" ::: "memory");
        } else {
            asm volatile("cp.async.wait_group 0;" ::: "memory");
        }
        __syncthreads();

        const uint32_t sA_ = baseA + sidx * STAGE_H * 2;
        const uint32_t sB_ = baseB + sidx * STAGE_H * 2;

        #pragma unroll
        for (int kk = 0; kk < 32; kk += 16) {
            uint32_t af[4][4];
            #pragma unroll
            for (int mt = 0; mt < 4; mt++) {
                const int r = warp_m * 64 + mt * 16 + (lq & 1) * 8 + lr;
                const uint32_t addr = sA_ + (r * 40 + kk + (lq >> 1) * 8) * 2;
                LDSM_X4(af[mt][0], af[mt][1], af[mt][2], af[mt][3], addr);
            }
            uint32_t bf[2][4];
            #pragma unroll
            for (int np = 0; np < 2; np++) {
                const int n = warp_n * 32 + np * 16 + (lq >> 1) * 8 + lr;
                const uint32_t addr = sB_ + (n * 40 + kk + (lq & 1) * 8) * 2;
                LDSM_X4(bf[np][0], bf[np][1], bf[np][2], bf[np][3], addr);
            }
            #pragma unroll
            for (int mt = 0; mt < 4; mt++)
                #pragma unroll
                for (int nt = 0; nt < 4; nt++)
                    mma16816(acc[mt][nt], af[mt], &bf[nt >> 1][(nt & 1) * 2]);
        }
        __syncthreads();
        sidx = (sidx + 1) % 3;
    }

    // ---- epilogue ----
    if (flags & F_HALFOUT) {
        __half* C = (__half*)Cv + (long long)blockIdx.z * sC;
        #pragma unroll
        for (int mt = 0; mt < 4; mt++)
            #pragma unroll
            for (int nt = 0; nt < 4; nt++) {
                const int r = row0 + warp_m * 64 + mt * 16 + lg;
                const int c = col0 + warp_n * 32 + nt * 8 + 2 * lt;
                if (c + 1 < N) {
                    if (r < M)
                        *(__half2*)(C + (size_t)r * ldc + c) =
                            __floats2half2_rn(acc[mt][nt][0], acc[mt][nt][1]);
                    if (r + 8 < M)
                        *(__half2*)(C + (size_t)(r + 8) * ldc + c) =
                            __floats2half2_rn(acc[mt][nt][2], acc[mt][nt][3]);
                }
            }
    } else {
        float* C = (float*)Cv + (long long)blockIdx.z * sC;
        #pragma unroll
        for (int mt = 0; mt < 4; mt++)
            #pragma unroll
            for (int nt = 0; nt < 4; nt++) {
                const int r = row0 + warp_m * 64 + mt * 16 + lg;
                const int c = col0 + warp_n * 32 + nt * 8 + 2 * lt;
                if (c + 1 < N) {
                    if (r < M)
                        *(float2*)(C + (size_t)r * ldc + c) =
                            make_float2(acc[mt][nt][0], acc[mt][nt][1]);
                    if (r + 8 < M)
                        *(float2*)(C + (size_t)(r + 8) * ldc + c) =
                            make_float2(acc[mt][nt][2], acc[mt][nt][3]);
                }
            }
    }
}

// ---------------- f32 -> f16 convert ----------------
__global__ void cvt_f2h(const float* __restrict__ src, __half* __restrict__ dst, int n)
{
    int i = (blockIdx.x * blockDim.x + threadIdx.x) * 4;
    if (i < n) {
        float4 v = *(const float4*)(src + i);
        *(__half2*)(dst + i)     = __floats2half2_rn(v.x, v.y);
        *(__half2*)(dst + i + 2) = __floats2half2_rn(v.z, v.w);
    }
}

// ---------------- transpose f32 -> f16: dst[c][r] = src[r][c] ----------------
__global__ void transpose_kh(const float* __restrict__ src, int ld_src,
                             __half* __restrict__ dst, int R, int Cc)
{
    __shared__ float t[32][33];
    const int c0 = blockIdx.x * 32, r0 = blockIdx.y * 32;
    const int x = threadIdx.x, y = threadIdx.y;
    #pragma unroll
    for (int j = 0; j < 32; j += 8) {
        int r = r0 + y + j, c = c0 + x;
        t[y + j][x] = (r < R && c < Cc) ? src[(size_t)r * ld_src + c] : 0.f;
    }
    __syncthreads();
    #pragma unroll
    for (int j = 0; j < 32; j += 8) {
        int c = c0 + y + j, r = r0 + x;
        if (c < Cc && r < R) dst[(size_t)c * R + r] = __float2half(t[x][y + j]);
    }
}

// ---------------- w_uv -> [h][d][r] f16 ----------------
__global__ void transpose_wuv_h(const float* __restrict__ wuv)
{
    int idx = blockIdx.x * blockDim.x + threadIdx.x;
    if (idx < KV_LORA * NHEAD * D_V) {
        int r = idx >> 12;
        int h = (idx >> 7) & 31;
        int d = idx & 127;
        h_wuvT[((size_t)(h * 128 + d)) * KV_LORA + r] = __float2half(wuv[idx]);
    }
}

// ---------------- reductions ----------------
__device__ __forceinline__ float block_reduce_sum(float v, float* red)
{
    __syncthreads();
    const int lane = threadIdx.x & 31, wid = threadIdx.x >> 5;
    #pragma unroll
    for (int o = 16; o > 0; o >>= 1) v += __shfl_xor_sync(0xffffffffu, v, o);
    if (lane == 0) red[wid] = v;
    __syncthreads();
    const int nw = blockDim.x >> 5;
    float s = (threadIdx.x < nw) ? red[threadIdx.x] : 0.f;
    if (wid == 0) {
        #pragma unroll
        for (int o = 16; o > 0; o >>= 1) s += __shfl_xor_sync(0xffffffffu, s, o);
        if (lane == 0) red[0] = s;
    }
    __syncthreads();
    return red[0];
}

__device__ __forceinline__ float block_reduce_max(float v, float* red)
{
    __syncthreads();
    const int lane = threadIdx.x & 31, wid = threadIdx.x >> 5;
    #pragma unroll
    for (int o = 16; o > 0; o >>= 1) v = fmaxf(v, __shfl_xor_sync(0xffffffffu, v, o));
    if (lane == 0) red[wid] = v;
    __syncthreads();
    const int nw = blockDim.x >> 5;
    float s = (threadIdx.x < nw) ? red[threadIdx.x] : -3.0e38f;
    if (wid == 0) {
        #pragma unroll
        for (int o = 16; o > 0; o >>= 1) s = fmaxf(s, __shfl_xor_sync(0xffffffffu, s, o));
        if (lane == 0) red[0] = s;
    }
    __syncthreads();
    return red[0];
}

// ---------------- softmax: one global read (row cached in smem), f16 out ----------------
__global__ void softmax_kernel()
{
    __shared__ float red[32];
    __shared__ float buf[T_SEQ];
    const int t = blockIdx.x;
    const int h = blockIdx.y;
    const float* row = g_scores + ((size_t)h * T_SEQ + t) * T_SEQ;
    __half* orow = h_probs + ((size_t)h * T_SEQ + t) * T_SEQ;
    const int n = t + 1;
    const float scale = rsqrtf(192.0f);

    float m = -3.0e38f;
    for (int i = threadIdx.x; i < n; i += blockDim.x) {
        float v = row[i] * scale;
        buf[i] = v;
        m = fmaxf(m, v);
    }
    m = block_reduce_max(m, red);

    float l = 0.f;
    for (int i = threadIdx.x; i < n; i += blockDim.x) l += __expf(buf[i] - m);
    l = block_reduce_sum(l, red);
    const float inv = 1.0f / l;

    const int kblk = ((t >> 7) + 1) << 7;
    for (int i = threadIdx.x; i < kblk; i += blockDim.x)
        orow[i] = __float2half((i < n) ? __expf(buf[i] - m) * inv : 0.f);
}

// ---------------- rmsnorm: f32 in -> f16 out ----------------
__global__ void rmsnorm_h(const float* __restrict__ x, const float* __restrict__ scale,
                          __half* __restrict__ out, int N)
{
    __shared__ float red[32];
    const float* xr = x + (size_t)blockIdx.x * N;
    __half* orow = out + (size_t)blockIdx.x * N;
    float ss = 0.f;
    for (int i = threadIdx.x; i < N; i += blockDim.x) { float v = xr[i]; ss += v * v; }
    float tot = block_reduce_sum(ss, red);
    float r = rsqrtf(tot / (float)N + EPS_RMS);
    for (int i = threadIdx.x; i < N; i += blockDim.x)
        orow[i] = __float2half(xr[i] * r * scale[i]);
}

// ---------------- kv post: rmsnorm -> caug[:,0:512]; rope -> caug[:,512:576] (f32) ----------------
__global__ void kv_post_kernel(const int* __restrict__ pos, const float* __restrict__ scale)
{
    __shared__ float red[32];
    const int t = blockIdx.x;
    const float* row = g_kva + (size_t)t * D_AUG;
    float* crow = g_caug + (size_t)t * D_AUG;
    float ss = 0.f;
    for (int i = threadIdx.x; i < KV_LORA; i += blockDim.x) { float v = row[i]; ss += v * v; }
    float tot = block_reduce_sum(ss, red);
    float r = rsqrtf(tot / (float)KV_LORA + EPS_RMS);
    for (int i = threadIdx.x; i < KV_LORA; i += blockDim.x)
        crow[i] = row[i] * r * scale[i];
    if (threadIdx.x < D_ROPE / 2) {
        int i = threadIdx.x;
        float p = (float)pos[t];
        float inv = __powf(10000.0f, -(float)i * (1.0f / 32.0f));
        float ang = p * inv;
        float c = cosf(ang), s = sinf(ang);
        float x1 = row[KV_LORA + 2*i], x2 = row[KV_LORA + 2*i + 1];
        crow[KV_LORA + 2*i    ] = x1 * c - x2 * s;
        crow[KV_LORA + 2*i + 1] = x1 * s + x2 * c;
    }
}

// ---------------- fused q rope + f16 convert: g_q (f32) -> h_q (f16, rope applied) ----------------
__global__ void q_rope_cvt(const int* __restrict__ pos)
{
    const int t = blockIdx.x;
    const float p = (float)pos[t];
    const float* src = g_q + (size_t)t * (NHEAD * D_QK);
    __half* dst = h_q + (size_t)t * (NHEAD * D_QK);
    for (int idx = threadIdx.x; idx < NHEAD * D_QK / 2; idx += blockDim.x) {
        const int c = idx * 2;
        const int o = c % D_QK;
        float x1 = src[c], x2 = src[c + 1];
        if (o >= D_NOPE) {
            const int j = (o - D_NOPE) >> 1;
            float inv = __powf(10000.0f, -(float)j * (1.0f / 32.0f));
            float ang = p * inv;
            float cc = cosf(ang), ss = sinf(ang);
            float y1 = x1 * cc - x2 * ss;
            float y2 = x1 * ss + x2 * cc;
            x1 = y1; x2 = y2;
        }
        *(__half2*)(dst + c) = __floats2half2_rn(x1, x2);
    }
}

// ---------------- copy roped q into h_qaug[:, 512:576] ----------------
__global__ void qaug_rope_kernel()
{
    const int t = blockIdx.x;
    for (int idx = threadIdx.x; idx < NHEAD * D_ROPE; idx += blockDim.x) {
        int h = idx >> 6, k = idx & 63;
        h_qaug[((size_t)h * T_SEQ + t) * D_AUG + KV_LORA + k] =
            h_q[(size_t)t * (NHEAD * D_QK) + h * D_QK + D_NOPE + k];
    }
}

// ---------------- host launcher ----------------
extern "C" void kernel_launch(void* const* d_in, const int* in_sizes, int n_in,
                              void* d_out, int out_size)
{
    const float* hs     = (const float*)d_in[0];
    const int*   pos    = (const int*)  d_in[1];
    const float* w_qa   = (const float*)d_in[2];
    const float* qa_ln  = (const float*)d_in[3];
    const float* w_qb   = (const float*)d_in[4];
    const float* w_kva  = (const float*)d_in[5];
    const float* kva_ln = (const float*)d_in[6];
    const float* w_uk   = (const float*)d_in[7];
    const float* w_uv   = (const float*)d_in[8];
    const float* w_o    = (const float*)d_in[9];
    float* out = (float*)d_out;

    float  *p_qc, *p_q, *p_kva, *p_caug, *p_scores;
    __half *p_hs, *p_hqc, *p_hq, *p_hwuk, *p_hqaug, *p_hcaug, *p_hcompT,
           *p_hprobs, *p_hol, *p_hov, *p_wqaT, *p_wqbT, *p_wkvaT, *p_woT, *p_wuvT;
    cudaGetSymbolAddress((void**)&p_qc,     g_qc);
    cudaGetSymbolAddress((void**)&p_q,      g_q);
    cudaGetSymbolAddress((void**)&p_kva,    g_kva);
    cudaGetSymbolAddress((void**)&p_caug,   g_caug);
    cudaGetSymbolAddress((void**)&p_scores, g_scores);
    cudaGetSymbolAddress((void**)&p_hs,     h_hs);
    cudaGetSymbolAddress((void**)&p_hqc,    h_qc);
    cudaGetSymbolAddress((void**)&p_hq,     h_q);
    cudaGetSymbolAddress((void**)&p_hwuk,   h_wuk);
    cudaGetSymbolAddress((void**)&p_hqaug,  h_qaug);
    cudaGetSymbolAddress((void**)&p_hcaug,  h_caug);
    cudaGetSymbolAddress((void**)&p_hcompT, h_compT);
    cudaGetSymbolAddress((void**)&p_hprobs, h_probs);
    cudaGetSymbolAddress((void**)&p_hol,    h_ol);
    cudaGetSymbolAddress((void**)&p_hov,    h_ov);
    cudaGetSymbolAddress((void**)&p_wqaT,   h_wqaT);
    cudaGetSymbolAddress((void**)&p_wqbT,   h_wqbT);
    cudaGetSymbolAddress((void**)&p_wkvaT,  h_wkvaT);
    cudaGetSymbolAddress((void**)&p_woT,    h_woT);
    cudaGetSymbolAddress((void**)&p_wuvT,   h_wuvT);

    cudaFuncSetAttribute(hgemm, cudaFuncAttributeMaxDynamicSharedMemorySize, HG_SMEM);

    dim3 tb(32, 8);
    // operand prep (f16 conversions / transposes)
    cvt_f2h<<<(T_SEQ*HID/4 + 255)/256, 256>>>(hs, p_hs, T_SEQ*HID);
    transpose_kh<<<dim3(Q_LORA/32, HID/32), tb>>>(w_qa, Q_LORA, p_wqaT, HID, Q_LORA);
    transpose_kh<<<dim3((NHEAD*D_QK)/32, Q_LORA/32), tb>>>(w_qb, NHEAD*D_QK, p_wqbT, Q_LORA, NHEAD*D_QK);
    transpose_kh<<<dim3(D_AUG/32, HID/32), tb>>>(w_kva, D_AUG, p_wkvaT, HID, D_AUG);
    transpose_kh<<<dim3(HID/32, HID/32), tb>>>(w_o, HID, p_woT, HID, HID);
    cvt_f2h<<<(KV_LORA*NHEAD*D_NOPE/4 + 255)/256, 256>>>(w_uk, p_hwuk, KV_LORA*NHEAD*D_NOPE);
    transpose_wuv_h<<<(KV_LORA*NHEAD*D_V + 255)/256, 256>>>(w_uv);

    // q_c = rmsnorm(hs @ w_qa) -> f16
    hgemm<<<dim3(Q_LORA/128, T_SEQ/128, 1), 256, HG_SMEM>>>(
        p_hs, HID, 0, p_wqaT, HID, 0, p_qc, Q_LORA, 0, T_SEQ, Q_LORA, HID, 0);
    rmsnorm_h<<<T_SEQ, 256>>>(p_qc, qa_ln, p_hqc, Q_LORA);

    // q = q_c @ w_qb (f32), fused rope + convert -> h_q
    hgemm<<<dim3((NHEAD*D_QK)/128, T_SEQ/128, 1), 256, HG_SMEM>>>(
        p_hqc, Q_LORA, 0, p_wqbT, Q_LORA, 0, p_q, NHEAD*D_QK, 0,
        T_SEQ, NHEAD*D_QK, Q_LORA, 0);
    q_rope_cvt<<<T_SEQ, 256>>>(pos);

    // qaug[h][:,0:512] = q_nope[:,h,:] @ w_uk[:,h,:]^T  -> f16
    hgemm<<<dim3(KV_LORA/128, T_SEQ/128, NHEAD), 256, HG_SMEM>>>(
        p_hq, NHEAD*D_QK, (long long)D_QK,
        p_hwuk, NHEAD*D_NOPE, (long long)D_NOPE,
        p_hqaug, D_AUG, (long long)T_SEQ*D_AUG,
        T_SEQ, KV_LORA, D_NOPE, F_HALFOUT);
    qaug_rope_kernel<<<T_SEQ, 256>>>();

    // kv_a = hs @ w_kva (f32), then rmsnorm+rope -> caug f32 -> f16 (+transposed)
    hgemm<<<dim3((D_AUG+127)/128, T_SEQ/128, 1), 256, HG_SMEM>>>(
        p_hs, HID, 0, p_wkvaT, HID, 0, p_kva, D_AUG, 0, T_SEQ, D_AUG, HID, 0);
    kv_post_kernel<<<T_SEQ, 256>>>(pos, kva_ln);
    cvt_f2h<<<(T_SEQ*D_AUG/4 + 255)/256, 256>>>(p_caug, p_hcaug, T_SEQ*D_AUG);
    transpose_kh<<<dim3(KV_LORA/32, T_SEQ/32), tb>>>(p_caug, D_AUG, p_hcompT, T_SEQ, KV_LORA);

    // scores[h] = Qaug[h] @ Caug^T  (f32 out, causal block skip)
    hgemm<<<dim3(T_SEQ/128, T_SEQ/128, NHEAD), 256, HG_SMEM>>>(
        p_hqaug, D_AUG, (long long)T_SEQ*D_AUG,
        p_hcaug, D_AUG, 0,
        p_scores, T_SEQ, (long long)T_SEQ*T_SEQ,
        T_SEQ, T_SEQ, D_AUG, F_SKIP);

    // softmax -> f16 probs (zero-padded to 128 boundary)
    softmax_kernel<<<dim3(T_SEQ, NHEAD), 256>>>();

    // O[h] = P[h] @ comp  -> f16 (K capped at row0+128)
    hgemm<<<dim3(KV_LORA/128, T_SEQ/128, NHEAD), 256, HG_SMEM>>>(
        p_hprobs, T_SEQ, (long long)T_SEQ*T_SEQ,
        p_hcompT, T_SEQ, 0,
        p_hol, KV_LORA, (long long)T_SEQ*KV_LORA,
        T_SEQ, KV_LORA, T_SEQ, F_KCAUSAL | F_HALFOUT);

    // o_v[:, h*128:(h+1)*128] = O[h] @ w_uv[:,h,:]  -> f16
    hgemm<<<dim3(1, T_SEQ/128, NHEAD), 256, HG_SMEM>>>(
        p_hol, KV_LORA, (long long)T_SEQ*KV_LORA,
        p_wuvT, KV_LORA, (long long)D_V*KV_LORA,
        p_hov, NHEAD*D_V, (long long)D_V,
        T_SEQ, D_V, KV_LORA, F_HALFOUT);

    // out = o_v @ w_o (f32)
    hgemm<<<dim3(HID/128, T_SEQ/128, 1), 256, HG_SMEM>>>(
        p_hov, NHEAD*D_V, 0, p_woT, NHEAD*D_V, 0, out, HID, 0,
        T_SEQ, HID, NHEAD*D_V, 0);
}

// round 9
// speedup vs baseline: 10.9062x; 1.0419x over previous
#include <cuda_runtime.h>
#include <cuda_fp16.h>
#include <math.h>
#include <stdint.h>

#define T_SEQ   2048
#define HID     4096
#define NHEAD   32
#define Q_LORA  1536
#define KV_LORA 512
#define D_NOPE  128
#define D_ROPE  64
#define D_QK    192
#define D_V     128
#define D_AUG   576
#define EPS_RMS 1e-6f

#define F_KCAUSAL 1   // K_eff = row0 + 128 (PV with zero-padded P)
#define F_SKIP    4   // skip blocks fully above causal diagonal
#define F_HALFOUT 8   // C is __half*

// ---------------- scratch (device globals) ----------------
__device__ float  g_qc    [T_SEQ * Q_LORA];
__device__ float  g_q     [T_SEQ * NHEAD * D_QK];
__device__ float  g_kva   [T_SEQ * D_AUG];
__device__ float  g_caug  [T_SEQ * D_AUG];
__device__ float  g_scores[(size_t)NHEAD * T_SEQ * T_SEQ];       // [h][t][s] f32

__device__ __half h_hs    [T_SEQ * HID];
__device__ __half h_qc    [T_SEQ * Q_LORA];
__device__ __half h_q     [T_SEQ * NHEAD * D_QK];
__device__ __half h_wuk   [KV_LORA * NHEAD * D_NOPE];            // [r][h][d]
__device__ __half h_qaug  [(size_t)NHEAD * T_SEQ * D_AUG];       // [h][t][576]
__device__ __half h_caug  [T_SEQ * D_AUG];                       // [s][576]
__device__ __half h_compT [KV_LORA * T_SEQ];                     // [r][s]
__device__ __half h_probs [(size_t)NHEAD * T_SEQ * T_SEQ];       // [h][t][s]
__device__ __half h_ol    [(size_t)NHEAD * T_SEQ * KV_LORA];     // [h][t][r]
__device__ __half h_ov    [T_SEQ * NHEAD * D_V];
__device__ __half h_wqaT  [Q_LORA * HID];
__device__ __half h_wqbT  [(NHEAD*D_QK) * Q_LORA];
__device__ __half h_wkvaT [D_AUG * HID];
__device__ __half h_woT   [HID * HID];
__device__ __half h_wuvT  [NHEAD * D_V * KV_LORA];               // [h][d][r]

// ---------------- helpers ----------------
__device__ __forceinline__ uint32_t smem_u32(const void* p)
{
    uint32_t a;
    asm("{ .reg .u64 t; cvta.to.shared.u64 t, %1; cvt.u32.u64 %0, t; }" : "=r"(a) : "l"(p));
    return a;
}

__device__ __forceinline__ void mma16816(float c[4], const uint32_t a[4], const uint32_t b[2])
{
    asm volatile(
        "mma.sync.aligned.m16n8k16.row.col.f32.f16.f16.f32 "
        "{%0,%1,%2,%3}, {%4,%5,%6,%7}, {%8,%9}, {%0,%1,%2,%3};"
        : "+f"(c[0]), "+f"(c[1]), "+f"(c[2]), "+f"(c[3])
        : "r"(a[0]), "r"(a[1]), "r"(a[2]), "r"(a[3]), "r"(b[0]), "r"(b[1]));
}

#define LDSM_X4(r0, r1, r2, r3, addr) \
    asm volatile("ldmatrix.sync.aligned.m8n8.x4.shared.b16 {%0,%1,%2,%3}, [%4];" \
        : "=r"(r0), "=r"(r1), "=r"(r2), "=r"(r3) : "r"(addr))

__device__ __forceinline__ void cpa16(uint32_t dst, const void* src, int sz)
{
    asm volatile("cp.async.cg.shared.global [%0], [%1], 16, %2;"
        :: "r"(dst), "l"(src), "r"(sz) : "memory");
}

// load [128 rows][32 halves] tile into smem (stride 40 halves = 80B)
__device__ __forceinline__ void load_tile(
    const __half* __restrict__ src, int ld, int r0, int nvalid, int k0,
    uint32_t dst, int tid)
{
    const int row = tid >> 1;
    const int half32 = (tid & 1);
    const __half* g = src + (size_t)(r0 + row) * ld + k0 + half32 * 16;
    const uint32_t d = dst + row * 80 + half32 * 32;
    const int sz = ((r0 + row) < nvalid) ? 16 : 0;
    cpa16(d,      g,     sz);
    cpa16(d + 16, g + 8, sz);
}

// ---------------- FP16 tensor-core GEMM: C = A @ B^T (B NT: [n][k]) ----------------
// 128x128 tile, BK=32, 3-stage cp.async pipeline, ONE barrier per k-iter.
#define STAGE_H (128 * 40)            // halves per operand per stage
#define HG_SMEM (3 * STAGE_H * 2 * 2) // bytes total (A+B, 3 stages)

__global__ void __launch_bounds__(256, 2) hgemm(
    const __half* __restrict__ A, int lda, long long sA,
    const __half* __restrict__ B, int ldb, long long sB,
    void* __restrict__ Cv, int ldc, long long sC,
    int M, int N, int K, int flags)
{
    const int row0 = blockIdx.y * 128;
    const int col0 = blockIdx.x * 128;
    if ((flags & F_SKIP) && col0 > row0 + 127) return;
    A += (long long)blockIdx.z * sA;
    B += (long long)blockIdx.z * sB;

    extern __shared__ __half dsm[];
    const uint32_t baseA = smem_u32(dsm);
    const uint32_t baseB = baseA + 3 * STAGE_H * 2;

    const int tid    = threadIdx.x;
    const int lane   = tid & 31;
    const int wid    = tid >> 5;
    const int warp_m = wid >> 2;
    const int warp_n = wid & 3;
    const int lg     = lane >> 2;
    const int lt     = lane & 3;
    const int lq     = lane >> 3;
    const int lr     = lane & 7;

    const int Keff = (flags & F_KCAUSAL) ? (row0 + 128) : K;
    const int nk   = Keff >> 5;

    float acc[4][4][4];
    #pragma unroll
    for (int i = 0; i < 4; i++)
        #pragma unroll
        for (int j = 0; j < 4; j++)
            #pragma unroll
            for (int e = 0; e < 4; e++) acc[i][j][e] = 0.f;

    // preload stages 0,1
    load_tile(A, lda, row0, M, 0, baseA, tid);
    load_tile(B, ldb, col0, N, 0, baseB, tid);
    asm volatile("cp.async.commit_group;" ::: "memory");
    if (nk > 1) {
        load_tile(A, lda, row0, M, 32, baseA + STAGE_H * 2, tid);
        load_tile(B, ldb, col0, N, 32, baseB + STAGE_H * 2, tid);
        asm volatile("cp.async.commit_group;" ::: "memory");
    }

    int sidx = 0;  // stage of tile i
    for (int i = 0; i < nk; i++) {
        // wait for tile i's group, then a single barrier.
        if (i + 1 < nk) {
            asm volatile("cp.async.wait_group 1;" ::: "memory");
        } else {
            asm volatile("cp.async.wait_group 0;" ::: "memory");
        }
        __syncthreads();
        // Safe to overwrite stage (i+2)%3 == (i-1)%3: every warp past this
        // barrier has finished compute(i-1) by program order.
        if (i + 2 < nk) {
            const int s2 = (sidx + 2) % 3;
            load_tile(A, lda, row0, M, (i + 2) * 32, baseA + s2 * STAGE_H * 2, tid);
            load_tile(B, ldb, col0, N, (i + 2) * 32, baseB + s2 * STAGE_H * 2, tid);
            asm volatile("cp.async.commit_group;" ::: "memory");
        }

        const uint32_t sA_ = baseA + sidx * STAGE_H * 2;
        const uint32_t sB_ = baseB + sidx * STAGE_H * 2;

        #pragma unroll
        for (int kk = 0; kk < 32; kk += 16) {
            uint32_t af[4][4];
            #pragma unroll
            for (int mt = 0; mt < 4; mt++) {
                const int r = warp_m * 64 + mt * 16 + (lq & 1) * 8 + lr;
                const uint32_t addr = sA_ + (r * 40 + kk + (lq >> 1) * 8) * 2;
                LDSM_X4(af[mt][0], af[mt][1], af[mt][2], af[mt][3], addr);
            }
            uint32_t bf[2][4];
            #pragma unroll
            for (int np = 0; np < 2; np++) {
                const int n = warp_n * 32 + np * 16 + (lq >> 1) * 8 + lr;
                const uint32_t addr = sB_ + (n * 40 + kk + (lq & 1) * 8) * 2;
                LDSM_X4(bf[np][0], bf[np][1], bf[np][2], bf[np][3], addr);
            }
            #pragma unroll
            for (int mt = 0; mt < 4; mt++)
                #pragma unroll
                for (int nt = 0; nt < 4; nt++)
                    mma16816(acc[mt][nt], af[mt], &bf[nt >> 1][(nt & 1) * 2]);
        }
        sidx = (sidx + 1) % 3;
    }

    // ---- epilogue ----
    if (flags & F_HALFOUT) {
        __half* C = (__half*)Cv + (long long)blockIdx.z * sC;
        #pragma unroll
        for (int mt = 0; mt < 4; mt++)
            #pragma unroll
            for (int nt = 0; nt < 4; nt++) {
                const int r = row0 + warp_m * 64 + mt * 16 + lg;
                const int c = col0 + warp_n * 32 + nt * 8 + 2 * lt;
                if (c + 1 < N) {
                    if (r < M)
                        *(__half2*)(C + (size_t)r * ldc + c) =
                            __floats2half2_rn(acc[mt][nt][0], acc[mt][nt][1]);
                    if (r + 8 < M)
                        *(__half2*)(C + (size_t)(r + 8) * ldc + c) =
                            __floats2half2_rn(acc[mt][nt][2], acc[mt][nt][3]);
                }
            }
    } else {
        float* C = (float*)Cv + (long long)blockIdx.z * sC;
        #pragma unroll
        for (int mt = 0; mt < 4; mt++)
            #pragma unroll
            for (int nt = 0; nt < 4; nt++) {
                const int r = row0 + warp_m * 64 + mt * 16 + lg;
                const int c = col0 + warp_n * 32 + nt * 8 + 2 * lt;
                if (c + 1 < N) {
                    if (r < M)
                        *(float2*)(C + (size_t)r * ldc + c) =
                            make_float2(acc[mt][nt][0], acc[mt][nt][1]);
                    if (r + 8 < M)
                        *(float2*)(C + (size_t)(r + 8) * ldc + c) =
                            make_float2(acc[mt][nt][2], acc[mt][nt][3]);
                }
            }
    }
}

// ---------------- f32 -> f16 convert ----------------
__global__ void cvt_f2h(const float* __restrict__ src, __half* __restrict__ dst, int n)
{
    int i = (blockIdx.x * blockDim.x + threadIdx.x) * 4;
    if (i < n) {
        float4 v = *(const float4*)(src + i);
        *(__half2*)(dst + i)     = __floats2half2_rn(v.x, v.y);
        *(__half2*)(dst + i + 2) = __floats2half2_rn(v.z, v.w);
    }
}

// ---------------- transpose f32 -> f16: dst[c][r] = src[r][c] ----------------
__global__ void transpose_kh(const float* __restrict__ src, int ld_src,
                             __half* __restrict__ dst, int R, int Cc)
{
    __shared__ float t[32][33];
    const int c0 = blockIdx.x * 32, r0 = blockIdx.y * 32;
    const int x = threadIdx.x, y = threadIdx.y;
    #pragma unroll
    for (int j = 0; j < 32; j += 8) {
        int r = r0 + y + j, c = c0 + x;
        t[y + j][x] = (r < R && c < Cc) ? src[(size_t)r * ld_src + c] : 0.f;
    }
    __syncthreads();
    #pragma unroll
    for (int j = 0; j < 32; j += 8) {
        int c = c0 + y + j, r = r0 + x;
        if (c < Cc && r < R) dst[(size_t)c * R + r] = __float2half(t[x][y + j]);
    }
}

// ---------------- w_uv -> [h][d][r] f16 ----------------
__global__ void transpose_wuv_h(const float* __restrict__ wuv)
{
    int idx = blockIdx.x * blockDim.x + threadIdx.x;
    if (idx < KV_LORA * NHEAD * D_V) {
        int r = idx >> 12;
        int h = (idx >> 7) & 31;
        int d = idx & 127;
        h_wuvT[((size_t)(h * 128 + d)) * KV_LORA + r] = __float2half(wuv[idx]);
    }
}

// ---------------- reductions ----------------
__device__ __forceinline__ float block_reduce_sum(float v, float* red)
{
    __syncthreads();
    const int lane = threadIdx.x & 31, wid = threadIdx.x >> 5;
    #pragma unroll
    for (int o = 16; o > 0; o >>= 1) v += __shfl_xor_sync(0xffffffffu, v, o);
    if (lane == 0) red[wid] = v;
    __syncthreads();
    const int nw = blockDim.x >> 5;
    float s = (threadIdx.x < nw) ? red[threadIdx.x] : 0.f;
    if (wid == 0) {
        #pragma unroll
        for (int o = 16; o > 0; o >>= 1) s += __shfl_xor_sync(0xffffffffu, s, o);
        if (lane == 0) red[0] = s;
    }
    __syncthreads();
    return red[0];
}

__device__ __forceinline__ float block_reduce_max(float v, float* red)
{
    __syncthreads();
    const int lane = threadIdx.x & 31, wid = threadIdx.x >> 5;
    #pragma unroll
    for (int o = 16; o > 0; o >>= 1) v = fmaxf(v, __shfl_xor_sync(0xffffffffu, v, o));
    if (lane == 0) red[wid] = v;
    __syncthreads();
    const int nw = blockDim.x >> 5;
    float s = (threadIdx.x < nw) ? red[threadIdx.x] : -3.0e38f;
    if (wid == 0) {
        #pragma unroll
        for (int o = 16; o > 0; o >>= 1) s = fmaxf(s, __shfl_xor_sync(0xffffffffu, s, o));
        if (lane == 0) red[0] = s;
    }
    __syncthreads();
    return red[0];
}

// ---------------- softmax: one global read, ONE exp per element, f16 out ----------------
__global__ void softmax_kernel()
{
    __shared__ float red[32];
    __shared__ float buf[T_SEQ];
    const int t = blockIdx.x;
    const int h = blockIdx.y;
    const float* row = g_scores + ((size_t)h * T_SEQ + t) * T_SEQ;
    __half* orow = h_probs + ((size_t)h * T_SEQ + t) * T_SEQ;
    const int n = t + 1;
    const float scale = rsqrtf(192.0f);

    float m = -3.0e38f;
    for (int i = threadIdx.x; i < n; i += blockDim.x) {
        float v = row[i] * scale;
        buf[i] = v;
        m = fmaxf(m, v);
    }
    m = block_reduce_max(m, red);

    float l = 0.f;
    for (int i = threadIdx.x; i < n; i += blockDim.x) {
        float e = __expf(buf[i] - m);
        buf[i] = e;                  // store exp once
        l += e;
    }
    l = block_reduce_sum(l, red);
    const float inv = 1.0f / l;

    const int kblk = ((t >> 7) + 1) << 7;
    for (int i = threadIdx.x; i < kblk; i += blockDim.x)
        orow[i] = __float2half((i < n) ? buf[i] * inv : 0.f);
}

// ---------------- rmsnorm: f32 in -> f16 out ----------------
__global__ void rmsnorm_h(const float* __restrict__ x, const float* __restrict__ scale,
                          __half* __restrict__ out, int N)
{
    __shared__ float red[32];
    const float* xr = x + (size_t)blockIdx.x * N;
    __half* orow = out + (size_t)blockIdx.x * N;
    float ss = 0.f;
    for (int i = threadIdx.x; i < N; i += blockDim.x) { float v = xr[i]; ss += v * v; }
    float tot = block_reduce_sum(ss, red);
    float r = rsqrtf(tot / (float)N + EPS_RMS);
    for (int i = threadIdx.x; i < N; i += blockDim.x)
        orow[i] = __float2half(xr[i] * r * scale[i]);
}

// ---------------- kv post: rmsnorm -> caug[:,0:512]; rope -> caug[:,512:576] (f32) ----------------
__global__ void kv_post_kernel(const int* __restrict__ pos, const float* __restrict__ scale)
{
    __shared__ float red[32];
    const int t = blockIdx.x;
    const float* row = g_kva + (size_t)t * D_AUG;
    float* crow = g_caug + (size_t)t * D_AUG;
    float ss = 0.f;
    for (int i = threadIdx.x; i < KV_LORA; i += blockDim.x) { float v = row[i]; ss += v * v; }
    float tot = block_reduce_sum(ss, red);
    float r = rsqrtf(tot / (float)KV_LORA + EPS_RMS);
    for (int i = threadIdx.x; i < KV_LORA; i += blockDim.x)
        crow[i] = row[i] * r * scale[i];
    if (threadIdx.x < D_ROPE / 2) {
        int i = threadIdx.x;
        float p = (float)pos[t];
        float inv = __powf(10000.0f, -(float)i * (1.0f / 32.0f));
        float ang = p * inv;
        float c = cosf(ang), s = sinf(ang);
        float x1 = row[KV_LORA + 2*i], x2 = row[KV_LORA + 2*i + 1];
        crow[KV_LORA + 2*i    ] = x1 * c - x2 * s;
        crow[KV_LORA + 2*i + 1] = x1 * s + x2 * c;
    }
}

// ---------------- fused q rope + f16 convert: g_q (f32) -> h_q (f16, rope applied) ----------------
__global__ void q_rope_cvt(const int* __restrict__ pos)
{
    const int t = blockIdx.x;
    const float p = (float)pos[t];
    const float* src = g_q + (size_t)t * (NHEAD * D_QK);
    __half* dst = h_q + (size_t)t * (NHEAD * D_QK);
    for (int idx = threadIdx.x; idx < NHEAD * D_QK / 2; idx += blockDim.x) {
        const int c = idx * 2;
        const int o = c % D_QK;
        float x1 = src[c], x2 = src[c + 1];
        if (o >= D_NOPE) {
            const int j = (o - D_NOPE) >> 1;
            float inv = __powf(10000.0f, -(float)j * (1.0f / 32.0f));
            float ang = p * inv;
            float cc = cosf(ang), ss = sinf(ang);
            float y1 = x1 * cc - x2 * ss;
            float y2 = x1 * ss + x2 * cc;
            x1 = y1; x2 = y2;
        }
        *(__half2*)(dst + c) = __floats2half2_rn(x1, x2);
    }
}

// ---------------- copy roped q into h_qaug[:, 512:576] ----------------
__global__ void qaug_rope_kernel()
{
    const int t = blockIdx.x;
    for (int idx = threadIdx.x; idx < NHEAD * D_ROPE; idx += blockDim.x) {
        int h = idx >> 6, k = idx & 63;
        h_qaug[((size_t)h * T_SEQ + t) * D_AUG + KV_LORA + k] =
            h_q[(size_t)t * (NHEAD * D_QK) + h * D_QK + D_NOPE + k];
    }
}

// ---------------- host launcher ----------------
extern "C" void kernel_launch(void* const* d_in, const int* in_sizes, int n_in,
                              void* d_out, int out_size)
{
    const float* hs     = (const float*)d_in[0];
    const int*   pos    = (const int*)  d_in[1];
    const float* w_qa   = (const float*)d_in[2];
    const float* qa_ln  = (const float*)d_in[3];
    const float* w_qb   = (const float*)d_in[4];
    const float* w_kva  = (const float*)d_in[5];
    const float* kva_ln = (const float*)d_in[6];
    const float* w_uk   = (const float*)d_in[7];
    const float* w_uv   = (const float*)d_in[8];
    const float* w_o    = (const float*)d_in[9];
    float* out = (float*)d_out;

    float  *p_qc, *p_q, *p_kva, *p_caug, *p_scores;
    __half *p_hs, *p_hqc, *p_hq, *p_hwuk, *p_hqaug, *p_hcaug, *p_hcompT,
           *p_hprobs, *p_hol, *p_hov, *p_wqaT, *p_wqbT, *p_wkvaT, *p_woT, *p_wuvT;
    cudaGetSymbolAddress((void**)&p_qc,     g_qc);
    cudaGetSymbolAddress((void**)&p_q,      g_q);
    cudaGetSymbolAddress((void**)&p_kva,    g_kva);
    cudaGetSymbolAddress((void**)&p_caug,   g_caug);
    cudaGetSymbolAddress((void**)&p_scores, g_scores);
    cudaGetSymbolAddress((void**)&p_hs,     h_hs);
    cudaGetSymbolAddress((void**)&p_hqc,    h_qc);
    cudaGetSymbolAddress((void**)&p_hq,     h_q);
    cudaGetSymbolAddress((void**)&p_hwuk,   h_wuk);
    cudaGetSymbolAddress((void**)&p_hqaug,  h_qaug);
    cudaGetSymbolAddress((void**)&p_hcaug,  h_caug);
    cudaGetSymbolAddress((void**)&p_hcompT, h_compT);
    cudaGetSymbolAddress((void**)&p_hprobs, h_probs);
    cudaGetSymbolAddress((void**)&p_hol,    h_ol);
    cudaGetSymbolAddress((void**)&p_hov,    h_ov);
    cudaGetSymbolAddress((void**)&p_wqaT,   h_wqaT);
    cudaGetSymbolAddress((void**)&p_wqbT,   h_wqbT);
    cudaGetSymbolAddress((void**)&p_wkvaT,  h_wkvaT);
    cudaGetSymbolAddress((void**)&p_woT,    h_woT);
    cudaGetSymbolAddress((void**)&p_wuvT,   h_wuvT);

    cudaFuncSetAttribute(hgemm, cudaFuncAttributeMaxDynamicSharedMemorySize, HG_SMEM);

    dim3 tb(32, 8);
    // operand prep (f16 conversions / transposes)
    cvt_f2h<<<(T_SEQ*HID/4 + 255)/256, 256>>>(hs, p_hs, T_SEQ*HID);
    transpose_kh<<<dim3(Q_LORA/32, HID/32), tb>>>(w_qa, Q_LORA, p_wqaT, HID, Q_LORA);
    transpose_kh<<<dim3((NHEAD*D_QK)/32, Q_LORA/32), tb>>>(w_qb, NHEAD*D_QK, p_wqbT, Q_LORA, NHEAD*D_QK);
    transpose_kh<<<dim3(D_AUG/32, HID/32), tb>>>(w_kva, D_AUG, p_wkvaT, HID, D_AUG);
    transpose_kh<<<dim3(HID/32, HID/32), tb>>>(w_o, HID, p_woT, HID, HID);
    cvt_f2h<<<(KV_LORA*NHEAD*D_NOPE/4 + 255)/256, 256>>>(w_uk, p_hwuk, KV_LORA*NHEAD*D_NOPE);
    transpose_wuv_h<<<(KV_LORA*NHEAD*D_V + 255)/256, 256>>>(w_uv);

    // q_c = rmsnorm(hs @ w_qa) -> f16
    hgemm<<<dim3(Q_LORA/128, T_SEQ/128, 1), 256, HG_SMEM>>>(
        p_hs, HID, 0, p_wqaT, HID, 0, p_qc, Q_LORA, 0, T_SEQ, Q_LORA, HID, 0);
    rmsnorm_h<<<T_SEQ, 256>>>(p_qc, qa_ln, p_hqc, Q_LORA);

    // q = q_c @ w_qb (f32), fused rope + convert -> h_q
    hgemm<<<dim3((NHEAD*D_QK)/128, T_SEQ/128, 1), 256, HG_SMEM>>>(
        p_hqc, Q_LORA, 0, p_wqbT, Q_LORA, 0, p_q, NHEAD*D_QK, 0,
        T_SEQ, NHEAD*D_QK, Q_LORA, 0);
    q_rope_cvt<<<T_SEQ, 256>>>(pos);

    // qaug[h][:,0:512] = q_nope[:,h,:] @ w_uk[:,h,:]^T  -> f16
    hgemm<<<dim3(KV_LORA/128, T_SEQ/128, NHEAD), 256, HG_SMEM>>>(
        p_hq, NHEAD*D_QK, (long long)D_QK,
        p_hwuk, NHEAD*D_NOPE, (long long)D_NOPE,
        p_hqaug, D_AUG, (long long)T_SEQ*D_AUG,
        T_SEQ, KV_LORA, D_NOPE, F_HALFOUT);
    qaug_rope_kernel<<<T_SEQ, 256>>>();

    // kv_a = hs @ w_kva (f32), then rmsnorm+rope -> caug f32 -> f16 (+transposed)
    hgemm<<<dim3((D_AUG+127)/128, T_SEQ/128, 1), 256, HG_SMEM>>>(
        p_hs, HID, 0, p_wkvaT, HID, 0, p_kva, D_AUG, 0, T_SEQ, D_AUG, HID, 0);
    kv_post_kernel<<<T_SEQ, 256>>>(pos, kva_ln);
    cvt_f2h<<<(T_SEQ*D_AUG/4 + 255)/256, 256>>>(p_caug, p_hcaug, T_SEQ*D_AUG);
    transpose_kh<<<dim3(KV_LORA/32, T_SEQ/32), tb>>>(p_caug, D_AUG, p_hcompT, T_SEQ, KV_LORA);

    // scores[h] = Qaug[h] @ Caug^T  (f32 out, causal block skip)
    hgemm<<<dim3(T_SEQ/128, T_SEQ/128, NHEAD), 256, HG_SMEM>>>(
        p_hqaug, D_AUG, (long long)T_SEQ*D_AUG,
        p_hcaug, D_AUG, 0,
        p_scores, T_SEQ, (long long)T_SEQ*T_SEQ,
        T_SEQ, T_SEQ, D_AUG, F_SKIP);

    // softmax -> f16 probs (zero-padded to 128 boundary)
    softmax_kernel<<<dim3(T_SEQ, NHEAD), 256>>>();

    // O[h] = P[h] @ comp  -> f16 (K capped at row0+128)
    hgemm<<<dim3(KV_LORA/128, T_SEQ/128, NHEAD), 256, HG_SMEM>>>(
        p_hprobs, T_SEQ, (long long)T_SEQ*T_SEQ,
        p_hcompT, T_SEQ, 0,
        p_hol, KV_LORA, (long long)T_SEQ*KV_LORA,
        T_SEQ, KV_LORA, T_SEQ, F_KCAUSAL | F_HALFOUT);

    // o_v[:, h*128:(h+1)*128] = O[h] @ w_uv[:,h,:]  -> f16
    hgemm<<<dim3(1, T_SEQ/128, NHEAD), 256, HG_SMEM>>>(
        p_hol, KV_LORA, (long long)T_SEQ*KV_LORA,
        p_wuvT, KV_LORA, (long long)D_V*KV_LORA,
        p_hov, NHEAD*D_V, (long long)D_V,
        T_SEQ, D_V, KV_LORA, F_HALFOUT);

    // out = o_v @ w_o (f32)
    hgemm<<<dim3(HID/128, T_SEQ/128, 1), 256, HG_SMEM>>>(
        p_hov, NHEAD*D_V, 0, p_woT, NHEAD*D_V, 0, out, HID, 0,
        T_SEQ, HID, NHEAD*D_V, 0);
}